// round 2
// baseline (speedup 1.0000x reference)
#include <cuda_runtime.h>
#include <math.h>

#define Bb 2
#define Ss 1024
#define Dd 1024
#define Ee 64
#define Nn 16

// ---------------- scratch (no allocation allowed) ----------------
__device__ float g_Q[Bb * Ss * Dd];
__device__ float g_K[Bb * Ss * Dd];
__device__ float g_V[Bb * Ss * Dd];
__device__ float g_A[Bb * Ss * Ss];   // QK^T / sqrt(d), lower-tri valid
__device__ float g_P[Bb * Ss * Ss];   // aggregated probability matrix
__device__ float g_comb[Bb * Ss * Dd];
__device__ float g_w[Bb * Nn * Ss];   // influence, layout [B][N][S]

// ---------------- reductions ----------------
__device__ __forceinline__ float warpMax(float v) {
    #pragma unroll
    for (int o = 16; o; o >>= 1) v = fmaxf(v, __shfl_xor_sync(0xffffffffu, v, o));
    return v;
}
__device__ __forceinline__ float warpSum(float v) {
    #pragma unroll
    for (int o = 16; o; o >>= 1) v += __shfl_xor_sync(0xffffffffu, v, o);
    return v;
}
// 256-thread block reduce. red must have >= 9 floats.
__device__ __forceinline__ float blockReduce(float v, bool isMax, float* red) {
    int lane = threadIdx.x & 31, w = threadIdx.x >> 5;
    v = isMax ? warpMax(v) : warpSum(v);
    if (lane == 0) red[w] = v;
    __syncthreads();
    if (w == 0) {
        float t = (lane < 8) ? red[lane] : (isMax ? -1e30f : 0.0f);
        t = isMax ? warpMax(t) : warpSum(t);
        if (lane == 0) red[8] = t;
    }
    __syncthreads();
    return red[8];
}

// ---------------- SGEMM 128x128x8, 256 thr, 8x8 per thread ----------------
// MODE 0: C = alpha * A[M,K] @ B[K,N]          (normal)
// MODE 1: C = alpha * A[M,K] @ B[N,K]^T        (NT), skip tiles fully above diagonal
// MODE 2: C = alpha * A[M,K] @ B[K,N], K-loop truncated to the tile's last row+1 (causal A)
template <int MODE>
__global__ __launch_bounds__(256)
void sgemm_k(const float* __restrict__ Ag, const float* __restrict__ Bg,
             float* __restrict__ Cg, int M, int N, int K,
             long long sA, long long sB, long long sC, float alpha)
{
    constexpr int BM = 128, BN = 128, BK = 8, TM = 8, TN = 8;
    const int bz = blockIdx.z;
    const float* A = Ag + bz * sA;
    const float* B = Bg + bz * sB;
    float* C = Cg + bz * sC;
    const int by = blockIdx.y, bx = blockIdx.x;
    if (MODE == 1 && bx > by) return;            // fully-masked score tile
    int kEnd = K;
    if (MODE == 2) kEnd = min(K, (by + 1) * BM); // P rows are zero past diagonal

    __shared__ float As[BK][BM];
    __shared__ float Bs[BK][BN];
    const int tid = threadIdx.x;
    const int tRow = (tid / 16) * TM;
    const int tCol = (tid % 16) * TN;

    float acc[TM][TN];
    #pragma unroll
    for (int i = 0; i < TM; i++)
        #pragma unroll
        for (int j = 0; j < TN; j++) acc[i][j] = 0.0f;

    // tile-load indices: 128 rows x 8 cols via one float4 per thread
    const int aRow = tid / 2;
    const int aCol = (tid % 2) * 4;
    // normal B: 8 rows x 128 cols
    const int bRow = tid / 32;
    const int bCol = (tid % 32) * 4;

    const float* Abase = A + (long long)(by * BM) * K;
    const float* BbaseT = B + (long long)(bx * BN) * K;   // MODE 1
    for (int k0 = 0; k0 < kEnd; k0 += BK) {
        float4 av = *(const float4*)(Abase + (long long)aRow * K + k0 + aCol);
        As[aCol + 0][aRow] = av.x;
        As[aCol + 1][aRow] = av.y;
        As[aCol + 2][aRow] = av.z;
        As[aCol + 3][aRow] = av.w;
        if (MODE == 1) {
            float4 bv = *(const float4*)(BbaseT + (long long)aRow * K + k0 + aCol);
            Bs[aCol + 0][aRow] = bv.x;
            Bs[aCol + 1][aRow] = bv.y;
            Bs[aCol + 2][aRow] = bv.z;
            Bs[aCol + 3][aRow] = bv.w;
        } else {
            float4 bv = *(const float4*)(B + (long long)(k0 + bRow) * N + bx * BN + bCol);
            *(float4*)&Bs[bRow][bCol] = bv;
        }
        __syncthreads();
        #pragma unroll
        for (int kk = 0; kk < BK; kk++) {
            float ra[TM], rb[TN];
            #pragma unroll
            for (int i = 0; i < TM; i++) ra[i] = As[kk][tRow + i];
            #pragma unroll
            for (int j = 0; j < TN; j++) rb[j] = Bs[kk][tCol + j];
            #pragma unroll
            for (int i = 0; i < TM; i++)
                #pragma unroll
                for (int j = 0; j < TN; j++) acc[i][j] += ra[i] * rb[j];
        }
        __syncthreads();
    }
    #pragma unroll
    for (int i = 0; i < TM; i++) {
        long long row = (long long)(by * BM + tRow + i);
        #pragma unroll
        for (int j = 0; j < TN; j += 4) {
            float4 v = make_float4(acc[i][j] * alpha, acc[i][j + 1] * alpha,
                                   acc[i][j + 2] * alpha, acc[i][j + 3] * alpha);
            *(float4*)(C + row * N + bx * BN + tCol + j) = v;
        }
    }
}

// ---------------- positions + splat influence ----------------
// one block per token (b*S+s), 64 threads (one per embedding dim e)
__global__ __launch_bounds__(64)
void pos_influence_kernel(const float* __restrict__ x, const float* __restrict__ posW,
                          const float* __restrict__ posB, const float* __restrict__ posBias,
                          const float* __restrict__ splatPos, const float* __restrict__ logScales,
                          float* __restrict__ wout)
{
    const int t = blockIdx.x;           // 0..B*S-1
    const int b = t / Ss, s = t % Ss;
    __shared__ float xs[Dd];
    __shared__ float pos[Ee];
    const int e = threadIdx.x;
    for (int i = e; i < Dd; i += 64) xs[i] = x[(long long)t * Dd + i];
    __syncthreads();
    float acc = posB[e];
    #pragma unroll 4
    for (int d = 0; d < Dd; d++) acc += xs[d] * posW[d * Ee + e];
    pos[e] = tanhf(acc) + posBias[s * Ee + e];
    __syncthreads();
    if (e < Nn) {
        float sc = expf(logScales[e]);
        sc = fminf(fmaxf(sc, 0.3f), 2.0f);
        float dsq = 0.0f;
        #pragma unroll
        for (int j = 0; j < Ee; j++) {
            float d = pos[j] - splatPos[e * Ee + j];
            dsq += d * d;
        }
        float inf = fmaxf(__expf(-0.5f * dsq / (sc * sc)), 0.01f);
        wout[((long long)b * Nn + e) * Ss + s] = inf;
    }
}

// ---------------- aggregated softmax: P̄ = (1/N) Σ_n g_n softmax_n ----------------
// one block per row (b*S+i), 256 threads
__global__ __launch_bounds__(256)
void pbar_kernel(const float* __restrict__ Abuf, const float* __restrict__ wbuf,
                 const float* __restrict__ gates, float* __restrict__ Pbar)
{
    const int row = blockIdx.x;
    const int b = row / Ss, i = row % Ss;
    const float* Arow = Abuf + ((long long)b * Ss + i) * Ss;
    __shared__ float sA[Ss];
    __shared__ float sE[Ss];
    __shared__ float sAcc[Ss];
    __shared__ float red[9];
    const int tid = threadIdx.x;
    const int len = i + 1;
    for (int j = tid; j < len; j += 256) { sA[j] = Arow[j]; sAcc[j] = 0.0f; }
    __syncthreads();
    #pragma unroll 1
    for (int n = 0; n < Nn; n++) {
        const float* wrow = wbuf + ((long long)b * Nn + n) * Ss;
        const float wi = wrow[i];
        float m = -1e30f;
        for (int j = tid; j < len; j += 256) {
            float t = wi * wrow[j] * sA[j];
            sE[j] = t;
            m = fmaxf(m, t);
        }
        m = blockReduce(m, true, red);
        float ssum = 0.0f;
        for (int j = tid; j < len; j += 256) {
            float e = __expf(sE[j] - m);
            sE[j] = e;
            ssum += e;
        }
        ssum = blockReduce(ssum, false, red);
        const float g = (1.0f / (1.0f + __expf(-gates[n]))) / (16.0f * ssum);
        for (int j = tid; j < len; j += 256) sAcc[j] += g * sE[j];
        __syncthreads();
    }
    float* Prow = Pbar + ((long long)b * Ss + i) * Ss;
    for (int j = tid; j < Ss; j += 256) Prow[j] = (j < len) ? sAcc[j] : 0.0f;
}

// ---------------- residual + LayerNorm ----------------
__global__ __launch_bounds__(256)
void final_ln_kernel(const float* __restrict__ x, const float* __restrict__ comb,
                     const float* __restrict__ rwp, const float* __restrict__ lnw,
                     const float* __restrict__ lnb, float* __restrict__ out)
{
    const int row = blockIdx.x;
    const int tid = threadIdx.x;
    __shared__ float red[9];
    const float rw = 1.0f / (1.0f + expf(-rwp[0]));
    const float om = 1.0f - rw;
    const float4 xv = ((const float4*)(x + (long long)row * Dd))[tid];
    const float4 cv = ((const float4*)(comb + (long long)row * Dd))[tid];
    float o0 = rw * xv.x + om * cv.x;
    float o1 = rw * xv.y + om * cv.y;
    float o2 = rw * xv.z + om * cv.z;
    float o3 = rw * xv.w + om * cv.w;
    float s = o0 + o1 + o2 + o3;
    float sq = o0 * o0 + o1 * o1 + o2 * o2 + o3 * o3;
    s = blockReduce(s, false, red);
    __syncthreads();
    sq = blockReduce(sq, false, red);
    const float mean = s * (1.0f / Dd);
    const float var = sq * (1.0f / Dd) - mean * mean;
    const float rstd = rsqrtf(var + 1e-5f);
    const float4 wv = ((const float4*)lnw)[tid];
    const float4 bv = ((const float4*)lnb)[tid];
    float4 ov;
    ov.x = (o0 - mean) * rstd * wv.x + bv.x;
    ov.y = (o1 - mean) * rstd * wv.y + bv.y;
    ov.z = (o2 - mean) * rstd * wv.z + bv.z;
    ov.w = (o3 - mean) * rstd * wv.w + bv.w;
    ((float4*)(out + (long long)row * Dd))[tid] = ov;
}

// ---------------- host launcher ----------------
extern "C" void kernel_launch(void* const* d_in, const int* in_sizes, int n_in,
                              void* d_out, int out_size)
{
    const float* x        = (const float*)d_in[0];   // [B,S,D]
    const float* posW     = (const float*)d_in[1];   // [D,E]
    const float* posB     = (const float*)d_in[2];   // [E]
    const float* posBias  = (const float*)d_in[3];   // [1024,E]
    const float* splatPos = (const float*)d_in[4];   // [N,E]
    const float* logSc    = (const float*)d_in[5];   // [N]
    const float* qW       = (const float*)d_in[6];   // [D,D]
    const float* kW       = (const float*)d_in[7];   // [D,D]
    const float* vW       = (const float*)d_in[8];   // [D,D]
    const float* gates    = (const float*)d_in[9];   // [N]
    const float* rwp      = (const float*)d_in[10];  // scalar
    const float* lnw      = (const float*)d_in[11];  // [D]
    const float* lnb      = (const float*)d_in[12];  // [D]
    float* out = (float*)d_out;

    float *Q, *K, *V, *A, *P, *comb, *w;
    cudaGetSymbolAddress((void**)&Q, g_Q);
    cudaGetSymbolAddress((void**)&K, g_K);
    cudaGetSymbolAddress((void**)&V, g_V);
    cudaGetSymbolAddress((void**)&A, g_A);
    cudaGetSymbolAddress((void**)&P, g_P);
    cudaGetSymbolAddress((void**)&comb, g_comb);
    cudaGetSymbolAddress((void**)&w, g_w);

    const int M = Bb * Ss;                 // 2048
    const float inv_sqrt_d = 1.0f / 32.0f; // 1/sqrt(1024)

    // positions + influence (independent of projections)
    pos_influence_kernel<<<M, 64>>>(x, posW, posB, posBias, splatPos, logSc, w);

    // Q,K,V projections: [2048,1024] @ [1024,1024]
    dim3 gProj(Dd / 128, M / 128, 1);
    sgemm_k<0><<<gProj, 256>>>(x, qW, Q, M, Dd, Dd, 0, 0, 0, 1.0f);
    sgemm_k<0><<<gProj, 256>>>(x, kW, K, M, Dd, Dd, 0, 0, 0, 1.0f);
    sgemm_k<0><<<gProj, 256>>>(x, vW, V, M, Dd, Dd, 0, 0, 0, 1.0f);

    // A = Q K^T / sqrt(d), per batch, lower-tri tiles only
    dim3 gScore(Ss / 128, Ss / 128, Bb);
    sgemm_k<1><<<gScore, 256>>>(Q, K, A, Ss, Ss, Dd,
                                (long long)Ss * Dd, (long long)Ss * Dd,
                                (long long)Ss * Ss, inv_sqrt_d);

    // aggregated softmax -> P̄
    pbar_kernel<<<M, 256>>>(A, w, gates, P);

    // comb = P̄ @ V (causal K-truncation)
    sgemm_k<2><<<gScore, 256>>>(P, V, comb, Ss, Dd, Ss,
                                (long long)Ss * Ss, (long long)Ss * Dd,
                                (long long)Ss * Dd, 1.0f);

    // residual + LayerNorm
    final_ln_kernel<<<M, 256>>>(x, comb, rwp, lnw, lnb, out);
}

// round 4
// speedup vs baseline: 2.2694x; 2.2694x over previous
#include <cuda_runtime.h>
#include <cuda_bf16.h>
#include <math.h>
#include <stdint.h>

#define Bb 2
#define Ss 1024
#define Dd 1024
#define Ee 64
#define Nn 16
#define Mtot (Bb * Ss)

// ---------------- scratch (no allocation allowed) ----------------
__device__ float g_A[Bb * Ss * Ss];        // QK^T/sqrt(d) fp32
__device__ float g_V[Bb * Ss * Dd];        // V fp32 (pre-transpose)
__device__ float g_comb[Bb * Ss * Dd];
__device__ float g_w[Bb * Nn * Ss];
__device__ __nv_bfloat16 g_xh[Mtot * Dd], g_xl[Mtot * Dd];
__device__ __nv_bfloat16 g_wqh[Dd * Dd], g_wql[Dd * Dd];
__device__ __nv_bfloat16 g_wkh[Dd * Dd], g_wkl[Dd * Dd];
__device__ __nv_bfloat16 g_wvh[Dd * Dd], g_wvl[Dd * Dd];
__device__ __nv_bfloat16 g_Qh[Mtot * Dd], g_Ql[Mtot * Dd];
__device__ __nv_bfloat16 g_Kh[Mtot * Dd], g_Kl[Mtot * Dd];
__device__ __nv_bfloat16 g_Vth[Bb * Dd * Ss], g_Vtl[Bb * Dd * Ss];
__device__ __nv_bfloat16 g_Ph[Bb * Ss * Ss], g_Pl[Bb * Ss * Ss];

// ---------------- helpers ----------------
__device__ __forceinline__ uint32_t smem_u32(const void* p) {
    uint32_t a;
    asm("{ .reg .u64 t; cvta.to.shared.u64 t, %1; cvt.u32.u64 %0, t; }" : "=r"(a) : "l"(p));
    return a;
}
// SW64 swizzle: 64B rows, XOR 16B-column bits [5:4] with row bits (off[8:7])
__device__ __forceinline__ uint32_t sw64(uint32_t off) { return off ^ ((off >> 3) & 0x30); }

__device__ __forceinline__ void split2(float v, __nv_bfloat16& h, __nv_bfloat16& l) {
    h = __float2bfloat16(v);
    l = __float2bfloat16(v - __bfloat162float(h));
}

#define CP_ASYNC16(s, g) \
    asm volatile("cp.async.cg.shared.global [%0], [%1], 16;" :: "r"(s), "l"(g) : "memory")
#define CP_COMMIT() asm volatile("cp.async.commit_group;" ::: "memory")
#define CP_WAIT2()  asm volatile("cp.async.wait_group 2;" ::: "memory")

#define LDSM_X4(r0, r1, r2, r3, addr) \
    asm volatile("ldmatrix.sync.aligned.m8n8.x4.shared.b16 {%0,%1,%2,%3}, [%4];" \
        : "=r"(r0), "=r"(r1), "=r"(r2), "=r"(r3) : "r"(addr) : "memory")

#define MMA16816(ac, a, b0, b1) \
    asm volatile("mma.sync.aligned.m16n8k16.row.col.f32.bf16.bf16.f32 " \
        "{%0,%1,%2,%3}, {%4,%5,%6,%7}, {%8,%9}, {%0,%1,%2,%3};" \
        : "+f"((ac)[0]), "+f"((ac)[1]), "+f"((ac)[2]), "+f"((ac)[3]) \
        : "r"((a)[0]), "r"((a)[1]), "r"((a)[2]), "r"((a)[3]), "r"(b0), "r"(b1))

// ---------------- reductions ----------------
__device__ __forceinline__ float warpSum(float v) {
    #pragma unroll
    for (int o = 16; o; o >>= 1) v += __shfl_xor_sync(0xffffffffu, v, o);
    return v;
}
__device__ __forceinline__ float blockSum(float v, float* red) {
    int lane = threadIdx.x & 31, w = threadIdx.x >> 5;
    v = warpSum(v);
    if (lane == 0) red[w] = v;
    __syncthreads();
    if (w == 0) {
        float t = (lane < 8) ? red[lane] : 0.0f;
        t = warpSum(t);
        if (lane == 0) red[8] = t;
    }
    __syncthreads();
    return red[8];
}

// ---------------- bf16x3 HMMA GEMM ----------------
// D[M,N] = alpha * A[M,K] @ B[N,K]^T, fp32 emulated via hiA*hiB + hiA*loB + loA*hiB.
// All three passes accumulate into the same fp32 fragments (K-loop extension).
#define BM 128
#define BN 128
#define BKC 32            // bf16 K elems per chunk (64B rows)
#define STAGE_BYTES (128 * 32 * 2)

struct GemmArgs {
    const __nv_bfloat16 *Ahi, *Alo; long long sA;
    const __nv_bfloat16 *Bhi0, *Bhi1, *Bhi2, *Blo0, *Blo1, *Blo2; long long sB;
    float *Cf0, *Cf1, *Cf2;
    __nv_bfloat16 *Chi0, *Chi1, *Chi2, *Clo0, *Clo1, *Clo2; long long sC;
    int M, N, K; float alpha;
};

// CAUSAL: 0=none, 1=skip tiles above diagonal (score), 2=K-truncate (PV)
template <int CAUSAL>
__global__ __launch_bounds__(256)
void hmma_gemm(GemmArgs g)
{
    const int bx = blockIdx.x, by = blockIdx.y, bz = blockIdx.z;
    if (CAUSAL == 1 && bx > by) return;
    int kEnd = g.K;
    if (CAUSAL == 2) kEnd = min(g.K, (by + 1) * BM);
    const int NC = kEnd / BKC;
    const int TOT = 3 * NC;

    __shared__ __align__(128) __nv_bfloat16 sA[3][BM * BKC];
    __shared__ __align__(128) __nv_bfloat16 sB[3][BN * BKC];
    const uint32_t sAb = smem_u32(&sA[0][0]);
    const uint32_t sBb = smem_u32(&sB[0][0]);

    const int tid = threadIdx.x, wid = tid >> 5, lane = tid & 31;
    const int warpM = wid >> 1, warpN = wid & 1;

    const __nv_bfloat16* Ah = g.Ahi + bz * g.sA;
    const __nv_bfloat16* Al = g.Alo + bz * g.sA;
    const __nv_bfloat16* Bh = (bz == 0 ? g.Bhi0 : bz == 1 ? g.Bhi1 : g.Bhi2) + bz * g.sB;
    const __nv_bfloat16* Bl = (bz == 0 ? g.Blo0 : bz == 1 ? g.Blo1 : g.Blo2) + bz * g.sB;

    float acc[2][8][4];
    #pragma unroll
    for (int i = 0; i < 2; i++)
        #pragma unroll
        for (int j = 0; j < 8; j++)
            #pragma unroll
            for (int k = 0; k < 4; k++) acc[i][j][k] = 0.0f;

    // per-thread load mapping: 512 x 16B units per tile, 2 per thread
    const int ldRow0 = tid >> 2;          // unit idx = tid   -> row, col
    const int ldC0   = (tid & 3) * 16;    // byte col within 64B row
    const int ldRow1 = (tid + 256) >> 2;
    const int ldC1   = ldC0;              // (tid+256)&3 == tid&3

    auto issue = [&](int it, int buf) {
        const int pass = it >= 2 * NC ? 2 : (it >= NC ? 1 : 0);
        const int k0 = (it - pass * NC) * BKC;
        const __nv_bfloat16* As = (pass == 2) ? Al : Ah;
        const __nv_bfloat16* Bs = (pass == 1) ? Bl : Bh;
        const __nv_bfloat16* Arow = As + (long long)(by * BM) * g.K + k0;
        const __nv_bfloat16* Brow = Bs + (long long)(bx * BN) * g.K + k0;
        const uint32_t aB = sAb + buf * STAGE_BYTES;
        const uint32_t bB = sBb + buf * STAGE_BYTES;
        CP_ASYNC16(aB + sw64(ldRow0 * 64 + ldC0), Arow + (long long)ldRow0 * g.K + (ldC0 >> 1));
        CP_ASYNC16(aB + sw64(ldRow1 * 64 + ldC1), Arow + (long long)ldRow1 * g.K + (ldC1 >> 1));
        CP_ASYNC16(bB + sw64(ldRow0 * 64 + ldC0), Brow + (long long)ldRow0 * g.K + (ldC0 >> 1));
        CP_ASYNC16(bB + sw64(ldRow1 * 64 + ldC1), Brow + (long long)ldRow1 * g.K + (ldC1 >> 1));
    };

    // prologue: 3 stages in flight
    #pragma unroll
    for (int it = 0; it < 3; it++) {
        if (it < TOT) issue(it, it);
        CP_COMMIT();
    }

    const int aRowL = (lane & 15);        // ldmatrix row-within-frag
    const int aHiK  = (lane >> 4);        // 0/1 -> k halves
    const int bRowL = ((lane & 16) >> 1) + (lane & 7);
    const int bHiK  = ((lane >> 3) & 1);

    #pragma unroll 1
    for (int it = 0; it < TOT; it++) {
        CP_WAIT2();
        __syncthreads();
        const int buf = it % 3;
        const uint32_t aB = sAb + buf * STAGE_BYTES;
        const uint32_t bB = sBb + buf * STAGE_BYTES;
        #pragma unroll
        for (int s = 0; s < 2; s++) {
            uint32_t ra[2][4], rb[4][4];
            #pragma unroll
            for (int mf = 0; mf < 2; mf++) {
                int row = warpM * 32 + mf * 16 + aRowL;
                int c16 = s * 2 + aHiK;
                uint32_t ad = aB + sw64(row * 64 + c16 * 16);
                LDSM_X4(ra[mf][0], ra[mf][1], ra[mf][2], ra[mf][3], ad);
            }
            #pragma unroll
            for (int ng = 0; ng < 4; ng++) {
                int nrow = warpN * 64 + ng * 16 + bRowL;
                int c16 = s * 2 + bHiK;
                uint32_t bd = bB + sw64(nrow * 64 + c16 * 16);
                LDSM_X4(rb[ng][0], rb[ng][1], rb[ng][2], rb[ng][3], bd);
            }
            #pragma unroll
            for (int mf = 0; mf < 2; mf++)
                #pragma unroll
                for (int ng = 0; ng < 4; ng++) {
                    MMA16816(acc[mf][ng * 2 + 0], ra[mf], rb[ng][0], rb[ng][1]);
                    MMA16816(acc[mf][ng * 2 + 1], ra[mf], rb[ng][2], rb[ng][3]);
                }
        }
        __syncthreads();
        const int nx = it + 3;
        if (nx < TOT) issue(nx, nx % 3);
        CP_COMMIT();
    }

    // ---------------- epilogue ----------------
    float* Cf = (bz == 0 ? g.Cf0 : bz == 1 ? g.Cf1 : g.Cf2);
    __nv_bfloat16* Chi = (bz == 0 ? g.Chi0 : bz == 1 ? g.Chi1 : g.Chi2);
    __nv_bfloat16* Clo = (bz == 0 ? g.Clo0 : bz == 1 ? g.Clo1 : g.Clo2);
    const float al = g.alpha;
    #pragma unroll
    for (int mf = 0; mf < 2; mf++) {
        const long long r0 = (long long)(by * BM + warpM * 32 + mf * 16 + (lane >> 2));
        const long long r1 = r0 + 8;
        #pragma unroll
        for (int nf = 0; nf < 8; nf++) {
            const int c0 = bx * BN + warpN * 64 + nf * 8 + (lane & 3) * 2;
            float v00 = acc[mf][nf][0] * al, v01 = acc[mf][nf][1] * al;
            float v10 = acc[mf][nf][2] * al, v11 = acc[mf][nf][3] * al;
            if (Chi) {
                __nv_bfloat16* ph0 = Chi + bz * g.sC + r0 * g.N + c0;
                __nv_bfloat16* pl0 = Clo + bz * g.sC + r0 * g.N + c0;
                __nv_bfloat16* ph1 = Chi + bz * g.sC + r1 * g.N + c0;
                __nv_bfloat16* pl1 = Clo + bz * g.sC + r1 * g.N + c0;
                __nv_bfloat16 h, l;
                __nv_bfloat162 hv, lv;
                split2(v00, h, l); hv.x = h; lv.x = l;
                split2(v01, h, l); hv.y = h; lv.y = l;
                *(__nv_bfloat162*)ph0 = hv; *(__nv_bfloat162*)pl0 = lv;
                split2(v10, h, l); hv.x = h; lv.x = l;
                split2(v11, h, l); hv.y = h; lv.y = l;
                *(__nv_bfloat162*)ph1 = hv; *(__nv_bfloat162*)pl1 = lv;
            } else {
                *(float2*)(Cf + bz * g.sC + r0 * g.N + c0) = make_float2(v00, v01);
                *(float2*)(Cf + bz * g.sC + r1 * g.N + c0) = make_float2(v10, v11);
            }
        }
    }
}

// ---------------- elementwise split ----------------
__global__ __launch_bounds__(256)
void split_kernel(const float* __restrict__ in, __nv_bfloat16* __restrict__ h,
                  __nv_bfloat16* __restrict__ l, int n)
{
    int i = blockIdx.x * 256 + threadIdx.x;
    if (i < n) { __nv_bfloat16 a, b; split2(in[i], a, b); h[i] = a; l[i] = b; }
}

// ---------------- transpose + split: out[c][r] = in[r][c] ----------------
__global__ __launch_bounds__(256)
void transpose_split(const float* __restrict__ in, __nv_bfloat16* __restrict__ oh,
                     __nv_bfloat16* __restrict__ ol, int rows, int cols,
                     long long sIn, long long sOut)
{
    const int b = blockIdx.z;
    in += b * sIn; oh += b * sOut; ol += b * sOut;
    __shared__ float t[32][33];
    const int c0 = blockIdx.x * 32, r0 = blockIdx.y * 32;
    const int x = threadIdx.x & 31, y = threadIdx.x >> 5;  // 32x8
    #pragma unroll
    for (int r = y; r < 32; r += 8) t[r][x] = in[(long long)(r0 + r) * cols + c0 + x];
    __syncthreads();
    #pragma unroll
    for (int r = y; r < 32; r += 8) {
        __nv_bfloat16 h, l;
        split2(t[x][r], h, l);
        oh[(long long)(c0 + r) * rows + r0 + x] = h;
        ol[(long long)(c0 + r) * rows + r0 + x] = l;
    }
}

// ---------------- positions + splat influence ----------------
__global__ __launch_bounds__(64)
void pos_influence_kernel(const float* __restrict__ x, const float* __restrict__ posW,
                          const float* __restrict__ posB, const float* __restrict__ posBias,
                          const float* __restrict__ splatPos, const float* __restrict__ logScales,
                          float* __restrict__ wout)
{
    const int t = blockIdx.x;
    const int b = t / Ss, s = t % Ss;
    __shared__ float xs[Dd];
    __shared__ float pos[Ee];
    const int e = threadIdx.x;
    for (int i = e; i < Dd; i += 64) xs[i] = x[(long long)t * Dd + i];
    __syncthreads();
    float acc = posB[e];
    #pragma unroll 4
    for (int d = 0; d < Dd; d++) acc += xs[d] * posW[d * Ee + e];
    pos[e] = tanhf(acc) + posBias[s * Ee + e];
    __syncthreads();
    if (e < Nn) {
        float sc = expf(logScales[e]);
        sc = fminf(fmaxf(sc, 0.3f), 2.0f);
        float dsq = 0.0f;
        #pragma unroll
        for (int j = 0; j < Ee; j++) {
            float d = pos[j] - splatPos[e * Ee + j];
            dsq += d * d;
        }
        float inf = fmaxf(__expf(-0.5f * dsq / (sc * sc)), 0.01f);
        wout[((long long)b * Nn + e) * Ss + s] = inf;
    }
}

// ---------------- aggregated softmax -> P̄ (bf16 hi/lo), register-resident ----------------
__global__ __launch_bounds__(256)
void pbar_kernel(const float* __restrict__ Abuf, const float* __restrict__ wbuf,
                 const float* __restrict__ gates, __nv_bfloat16* __restrict__ Phi,
                 __nv_bfloat16* __restrict__ Plo)
{
    const int row = blockIdx.x;
    const int b = row >> 10, i = row & 1023;
    const float* Arow = Abuf + ((long long)b << 20) + ((long long)i << 10);
    const int tid = threadIdx.x;
    const int len = i + 1;
    __shared__ float red[9];
    float aL[4], accL[4] = {0, 0, 0, 0};
    #pragma unroll
    for (int k = 0; k < 4; k++) {
        int j = tid + k * 256;
        aL[k] = (j < len) ? Arow[j] : 0.0f;
    }
    #pragma unroll 1
    for (int n = 0; n < Nn; n++) {
        const float* wrow = wbuf + (((long long)b * Nn + n) << 10);
        const float wi = wrow[i];
        float eL[4];
        float s = 0.0f;
        #pragma unroll
        for (int k = 0; k < 4; k++) {
            int j = tid + k * 256;
            if (j < len) {
                float e = __expf(wi * wrow[j] * aL[k]);  // |arg| small: no max shift needed
                eL[k] = e; s += e;
            } else eL[k] = 0.0f;
        }
        s = blockSum(s, red);
        const float gsc = (1.0f / (1.0f + __expf(-gates[n]))) / (16.0f * s);
        #pragma unroll
        for (int k = 0; k < 4; k++) accL[k] += gsc * eL[k];
    }
    __nv_bfloat16* ph = Phi + ((long long)b << 20) + ((long long)i << 10);
    __nv_bfloat16* pl = Plo + ((long long)b << 20) + ((long long)i << 10);
    #pragma unroll
    for (int k = 0; k < 4; k++) {
        int j = tid + k * 256;
        __nv_bfloat16 h, l;
        split2(accL[k], h, l);
        ph[j] = h; pl[j] = l;
    }
}

// ---------------- residual + LayerNorm ----------------
__global__ __launch_bounds__(256)
void final_ln_kernel(const float* __restrict__ x, const float* __restrict__ comb,
                     const float* __restrict__ rwp, const float* __restrict__ lnw,
                     const float* __restrict__ lnb, float* __restrict__ out)
{
    const int row = blockIdx.x;
    const int tid = threadIdx.x;
    __shared__ float red[9];
    const float rw = 1.0f / (1.0f + expf(-rwp[0]));
    const float om = 1.0f - rw;
    const float4 xv = ((const float4*)(x + (long long)row * Dd))[tid];
    const float4 cv = ((const float4*)(comb + (long long)row * Dd))[tid];
    float o0 = rw * xv.x + om * cv.x;
    float o1 = rw * xv.y + om * cv.y;
    float o2 = rw * xv.z + om * cv.z;
    float o3 = rw * xv.w + om * cv.w;
    float s = o0 + o1 + o2 + o3;
    float sq = o0 * o0 + o1 * o1 + o2 * o2 + o3 * o3;
    s = blockSum(s, red);
    __syncthreads();
    sq = blockSum(sq, red);
    const float mean = s * (1.0f / Dd);
    const float var = sq * (1.0f / Dd) - mean * mean;
    const float rstd = rsqrtf(var + 1e-5f);
    const float4 wv = ((const float4*)lnw)[tid];
    const float4 bv = ((const float4*)lnb)[tid];
    float4 ov;
    ov.x = (o0 - mean) * rstd * wv.x + bv.x;
    ov.y = (o1 - mean) * rstd * wv.y + bv.y;
    ov.z = (o2 - mean) * rstd * wv.z + bv.z;
    ov.w = (o3 - mean) * rstd * wv.w + bv.w;
    ((float4*)(out + (long long)row * Dd))[tid] = ov;
}

// ---------------- host launcher ----------------
extern "C" void kernel_launch(void* const* d_in, const int* in_sizes, int n_in,
                              void* d_out, int out_size)
{
    const float* x        = (const float*)d_in[0];
    const float* posW     = (const float*)d_in[1];
    const float* posB     = (const float*)d_in[2];
    const float* posBias  = (const float*)d_in[3];
    const float* splatPos = (const float*)d_in[4];
    const float* logSc    = (const float*)d_in[5];
    const float* qW       = (const float*)d_in[6];
    const float* kW       = (const float*)d_in[7];
    const float* vW       = (const float*)d_in[8];
    const float* gates    = (const float*)d_in[9];
    const float* rwp      = (const float*)d_in[10];
    const float* lnw      = (const float*)d_in[11];
    const float* lnb      = (const float*)d_in[12];
    float* out = (float*)d_out;

    float *A, *V, *comb, *w;
    __nv_bfloat16 *xh, *xl, *wqh, *wql, *wkh, *wkl, *wvh, *wvl;
    __nv_bfloat16 *Qh, *Ql, *Kh, *Kl, *Vth, *Vtl, *Ph, *Pl;
    cudaGetSymbolAddress((void**)&A, g_A);
    cudaGetSymbolAddress((void**)&V, g_V);
    cudaGetSymbolAddress((void**)&comb, g_comb);
    cudaGetSymbolAddress((void**)&w, g_w);
    cudaGetSymbolAddress((void**)&xh, g_xh);   cudaGetSymbolAddress((void**)&xl, g_xl);
    cudaGetSymbolAddress((void**)&wqh, g_wqh); cudaGetSymbolAddress((void**)&wql, g_wql);
    cudaGetSymbolAddress((void**)&wkh, g_wkh); cudaGetSymbolAddress((void**)&wkl, g_wkl);
    cudaGetSymbolAddress((void**)&wvh, g_wvh); cudaGetSymbolAddress((void**)&wvl, g_wvl);
    cudaGetSymbolAddress((void**)&Qh, g_Qh);   cudaGetSymbolAddress((void**)&Ql, g_Ql);
    cudaGetSymbolAddress((void**)&Kh, g_Kh);   cudaGetSymbolAddress((void**)&Kl, g_Kl);
    cudaGetSymbolAddress((void**)&Vth, g_Vth); cudaGetSymbolAddress((void**)&Vtl, g_Vtl);
    cudaGetSymbolAddress((void**)&Ph, g_Ph);   cudaGetSymbolAddress((void**)&Pl, g_Pl);

    const float inv_sqrt_d = 1.0f / 32.0f;

    // prep: influence, x split, W^T splits
    pos_influence_kernel<<<Mtot, 64>>>(x, posW, posB, posBias, splatPos, logSc, w);
    split_kernel<<<(Mtot * Dd) / 256, 256>>>(x, xh, xl, Mtot * Dd);
    dim3 gT(32, 32, 1);
    transpose_split<<<gT, 256>>>(qW, wqh, wql, Dd, Dd, 0, 0);
    transpose_split<<<gT, 256>>>(kW, wkh, wkl, Dd, Dd, 0, 0);
    transpose_split<<<gT, 256>>>(vW, wvh, wvl, Dd, Dd, 0, 0);

    // QKV projections: z = 0(Q,split) / 1(K,split) / 2(V,fp32)
    {
        GemmArgs a = {};
        a.Ahi = xh; a.Alo = xl; a.sA = 0;
        a.Bhi0 = wqh; a.Bhi1 = wkh; a.Bhi2 = wvh;
        a.Blo0 = wql; a.Blo1 = wkl; a.Blo2 = wvl; a.sB = 0;
        a.Cf2 = V;
        a.Chi0 = Qh; a.Chi1 = Kh; a.Clo0 = Ql; a.Clo1 = Kl; a.sC = 0;
        a.M = Mtot; a.N = Dd; a.K = Dd; a.alpha = 1.0f;
        hmma_gemm<0><<<dim3(Dd / BN, Mtot / BM, 3), 256>>>(a);
    }
    // V^T split (per batch)
    transpose_split<<<dim3(32, 32, Bb), 256>>>(V, Vth, Vtl, Ss, Dd,
                                               (long long)Ss * Dd, (long long)Dd * Ss);
    // scores A = Q K^T / sqrt(d), z = batch, lower-tri tiles only
    {
        GemmArgs a = {};
        a.Ahi = Qh; a.Alo = Ql; a.sA = (long long)Ss * Dd;
        a.Bhi0 = Kh; a.Bhi1 = Kh; a.Bhi2 = Kh;
        a.Blo0 = Kl; a.Blo1 = Kl; a.Blo2 = Kl; a.sB = (long long)Ss * Dd;
        a.Cf0 = A; a.Cf1 = A; a.Cf2 = A; a.sC = (long long)Ss * Ss;
        a.M = Ss; a.N = Ss; a.K = Dd; a.alpha = inv_sqrt_d;
        hmma_gemm<1><<<dim3(Ss / BN, Ss / BM, Bb), 256>>>(a);
    }
    // aggregated softmax -> P̄ hi/lo
    pbar_kernel<<<Mtot, 256>>>(A, w, gates, Ph, Pl);
    // comb = P̄ @ V  (B = V^T [D,S]), causal K-truncation
    {
        GemmArgs a = {};
        a.Ahi = Ph; a.Alo = Pl; a.sA = (long long)Ss * Ss;
        a.Bhi0 = Vth; a.Bhi1 = Vth; a.Bhi2 = Vth;
        a.Blo0 = Vtl; a.Blo1 = Vtl; a.Blo2 = Vtl; a.sB = (long long)Dd * Ss;
        a.Cf0 = comb; a.Cf1 = comb; a.Cf2 = comb; a.sC = (long long)Ss * Dd;
        a.M = Ss; a.N = Dd; a.K = Ss; a.alpha = 1.0f;
        hmma_gemm<2><<<dim3(Dd / BN, Ss / BM, Bb), 256>>>(a);
    }
    // residual + LayerNorm
    final_ln_kernel<<<Mtot, 256>>>(x, comb, rwp, lnw, lnb, out);
}

// round 5
// speedup vs baseline: 3.0830x; 1.3585x over previous
#include <cuda_runtime.h>
#include <cuda_bf16.h>
#include <math.h>
#include <stdint.h>

#define Bb 2
#define Ss 1024
#define Dd 1024
#define Ee 64
#define Nn 16
#define Mtot (Bb * Ss)

// ---------------- scratch (no allocation allowed) ----------------
__device__ float g_A[Bb * Ss * Ss];        // QK^T/sqrt(d) fp32
__device__ float g_V[Bb * Ss * Dd];        // V fp32 (pre-transpose)
__device__ float g_comb[Bb * Ss * Dd];
__device__ float g_w[Bb * Nn * Ss];
__device__ __nv_bfloat16 g_xh[Mtot * Dd];
__device__ __nv_bfloat16 g_wqh[Dd * Dd], g_wql[Dd * Dd];
__device__ __nv_bfloat16 g_wkh[Dd * Dd], g_wkl[Dd * Dd];
__device__ __nv_bfloat16 g_wvh[Dd * Dd], g_wvl[Dd * Dd];
__device__ __nv_bfloat16 g_Qh[Mtot * Dd], g_Ql[Mtot * Dd];
__device__ __nv_bfloat16 g_Kh[Mtot * Dd], g_Kl[Mtot * Dd];
__device__ __nv_bfloat16 g_Vth[Bb * Dd * Ss], g_Vtl[Bb * Dd * Ss];
__device__ __nv_bfloat16 g_Ph[Bb * Ss * Ss];

// ---------------- helpers ----------------
__device__ __forceinline__ uint32_t smem_u32(const void* p) {
    uint32_t a;
    asm("{ .reg .u64 t; cvta.to.shared.u64 t, %1; cvt.u32.u64 %0, t; }" : "=r"(a) : "l"(p));
    return a;
}
// SW64 swizzle: 64B rows, XOR 16B-column bits [5:4] with row bits (off[8:7])
__device__ __forceinline__ uint32_t sw64(uint32_t off) { return off ^ ((off >> 3) & 0x30); }

__device__ __forceinline__ void split2(float v, __nv_bfloat16& h, __nv_bfloat16& l) {
    h = __float2bfloat16(v);
    l = __float2bfloat16(v - __bfloat162float(h));
}

#define CP_ASYNC16(s, g) \
    asm volatile("cp.async.cg.shared.global [%0], [%1], 16;" :: "r"(s), "l"(g) : "memory")
#define CP_COMMIT() asm volatile("cp.async.commit_group;" ::: "memory")
#define CP_WAIT2()  asm volatile("cp.async.wait_group 2;" ::: "memory")

#define LDSM_X4(r0, r1, r2, r3, addr) \
    asm volatile("ldmatrix.sync.aligned.m8n8.x4.shared.b16 {%0,%1,%2,%3}, [%4];" \
        : "=r"(r0), "=r"(r1), "=r"(r2), "=r"(r3) : "r"(addr) : "memory")

#define MMA16816(ac, a, b0, b1) \
    asm volatile("mma.sync.aligned.m16n8k16.row.col.f32.bf16.bf16.f32 " \
        "{%0,%1,%2,%3}, {%4,%5,%6,%7}, {%8,%9}, {%0,%1,%2,%3};" \
        : "+f"((ac)[0]), "+f"((ac)[1]), "+f"((ac)[2]), "+f"((ac)[3]) \
        : "r"((a)[0]), "r"((a)[1]), "r"((a)[2]), "r"((a)[3]), "r"(b0), "r"(b1))

// ---------------- reductions ----------------
__device__ __forceinline__ float warpSum(float v) {
    #pragma unroll
    for (int o = 16; o; o >>= 1) v += __shfl_xor_sync(0xffffffffu, v, o);
    return v;
}
__device__ __forceinline__ float blockSum(float v, float* red) {
    int lane = threadIdx.x & 31, w = threadIdx.x >> 5;
    v = warpSum(v);
    if (lane == 0) red[w] = v;
    __syncthreads();
    if (w == 0) {
        float t = (lane < 8) ? red[lane] : 0.0f;
        t = warpSum(t);
        if (lane == 0) red[8] = t;
    }
    __syncthreads();
    return red[8];
}

// ---------------- bf16 multi-pass HMMA GEMM ----------------
// D[M,N] = alpha * A[M,K] @ B[N,K]^T
// NPASS=3: Ah*Bh + Ah*Bl + Al*Bh (fp32-emulated).  NPASS=2: Ah*Bh + Ah*Bl.
// All passes accumulate into the same fp32 fragments (K-loop extension).
#define BM 128
#define BN 128
#define BKC 32            // bf16 K elems per chunk (64B rows)
#define STAGE_BYTES (128 * 32 * 2)
#define NSTAGE 4
#define GSMEM (2 * NSTAGE * STAGE_BYTES)   // 65536

struct GemmArgs {
    const __nv_bfloat16 *Ahi, *Alo; long long sA;
    const __nv_bfloat16 *Bhi0, *Bhi1, *Bhi2, *Blo0, *Blo1, *Blo2; long long sB;
    float *Cf0, *Cf1, *Cf2;
    __nv_bfloat16 *Chi0, *Chi1, *Chi2, *Clo0, *Clo1, *Clo2; long long sC;
    int M, N, K; float alpha;
};

// CAUSAL: 0=none, 1=skip tiles above diagonal (score), 2=K-truncate (PV)
template <int CAUSAL, int NPASS>
__global__ __launch_bounds__(256)
void hmma_gemm(GemmArgs g)
{
    const int bx = blockIdx.x, by = blockIdx.y, bz = blockIdx.z;
    if (CAUSAL == 1 && bx > by) return;
    int kEnd = g.K;
    if (CAUSAL == 2) kEnd = min(g.K, (by + 1) * BM);
    const int NC = kEnd / BKC;
    const int TOT = NPASS * NC;

    extern __shared__ __align__(128) char dsm[];
    const uint32_t sAb = smem_u32(dsm);
    const uint32_t sBb = sAb + NSTAGE * STAGE_BYTES;

    const int tid = threadIdx.x, wid = tid >> 5, lane = tid & 31;
    const int warpM = wid >> 1, warpN = wid & 1;

    const __nv_bfloat16* Ah = g.Ahi + bz * g.sA;
    const __nv_bfloat16* Al = g.Alo + bz * g.sA;
    const __nv_bfloat16* Bh = (bz == 0 ? g.Bhi0 : bz == 1 ? g.Bhi1 : g.Bhi2) + bz * g.sB;
    const __nv_bfloat16* Bl = (bz == 0 ? g.Blo0 : bz == 1 ? g.Blo1 : g.Blo2) + bz * g.sB;

    float acc[2][8][4];
    #pragma unroll
    for (int i = 0; i < 2; i++)
        #pragma unroll
        for (int j = 0; j < 8; j++)
            #pragma unroll
            for (int k = 0; k < 4; k++) acc[i][j][k] = 0.0f;

    // per-thread load mapping: 512 x 16B units per tile, 2 per thread
    const int ldRow0 = tid >> 2;
    const int ldC0   = (tid & 3) * 16;
    const int ldRow1 = (tid + 256) >> 2;
    const int ldC1   = ldC0;

    auto issue = [&](int it, int buf) {
        const int pass = it / NC;
        const int k0 = (it - pass * NC) * BKC;
        const __nv_bfloat16* As = (NPASS == 3 && pass == 2) ? Al : Ah;
        const __nv_bfloat16* Bs = (pass == 1) ? Bl : Bh;
        const __nv_bfloat16* Arow = As + (long long)(by * BM) * g.K + k0;
        const __nv_bfloat16* Brow = Bs + (long long)(bx * BN) * g.K + k0;
        const uint32_t aB = sAb + buf * STAGE_BYTES;
        const uint32_t bB = sBb + buf * STAGE_BYTES;
        CP_ASYNC16(aB + sw64(ldRow0 * 64 + ldC0), Arow + (long long)ldRow0 * g.K + (ldC0 >> 1));
        CP_ASYNC16(aB + sw64(ldRow1 * 64 + ldC1), Arow + (long long)ldRow1 * g.K + (ldC1 >> 1));
        CP_ASYNC16(bB + sw64(ldRow0 * 64 + ldC0), Brow + (long long)ldRow0 * g.K + (ldC0 >> 1));
        CP_ASYNC16(bB + sw64(ldRow1 * 64 + ldC1), Brow + (long long)ldRow1 * g.K + (ldC1 >> 1));
    };

    // prologue: 3 stages in flight
    #pragma unroll
    for (int it = 0; it < 3; it++) {
        if (it < TOT) issue(it, it);
        CP_COMMIT();
    }

    const int aRowL = (lane & 15);
    const int aHiK  = (lane >> 4);
    const int bRowL = ((lane & 16) >> 1) + (lane & 7);
    const int bHiK  = ((lane >> 3) & 1);

    #pragma unroll 1
    for (int it = 0; it < TOT; it++) {
        CP_WAIT2();
        __syncthreads();
        // issue next chunk into buf (it+3)%4 == buf read at it-1; safe past the barrier
        const int nx = it + 3;
        if (nx < TOT) issue(nx, nx & 3);
        CP_COMMIT();
        const int buf = it & 3;
        const uint32_t aB = sAb + buf * STAGE_BYTES;
        const uint32_t bB = sBb + buf * STAGE_BYTES;
        #pragma unroll
        for (int s = 0; s < 2; s++) {
            uint32_t ra[2][4], rb[4][4];
            #pragma unroll
            for (int mf = 0; mf < 2; mf++) {
                int row = warpM * 32 + mf * 16 + aRowL;
                int c16 = s * 2 + aHiK;
                uint32_t ad = aB + sw64(row * 64 + c16 * 16);
                LDSM_X4(ra[mf][0], ra[mf][1], ra[mf][2], ra[mf][3], ad);
            }
            #pragma unroll
            for (int ng = 0; ng < 4; ng++) {
                int nrow = warpN * 64 + ng * 16 + bRowL;
                int c16 = s * 2 + bHiK;
                uint32_t bd = bB + sw64(nrow * 64 + c16 * 16);
                LDSM_X4(rb[ng][0], rb[ng][1], rb[ng][2], rb[ng][3], bd);
            }
            #pragma unroll
            for (int mf = 0; mf < 2; mf++)
                #pragma unroll
                for (int ng = 0; ng < 4; ng++) {
                    MMA16816(acc[mf][ng * 2 + 0], ra[mf], rb[ng][0], rb[ng][1]);
                    MMA16816(acc[mf][ng * 2 + 1], ra[mf], rb[ng][2], rb[ng][3]);
                }
        }
    }

    // ---------------- epilogue ----------------
    float* Cf = (bz == 0 ? g.Cf0 : bz == 1 ? g.Cf1 : g.Cf2);
    __nv_bfloat16* Chi = (bz == 0 ? g.Chi0 : bz == 1 ? g.Chi1 : g.Chi2);
    __nv_bfloat16* Clo = (bz == 0 ? g.Clo0 : bz == 1 ? g.Clo1 : g.Clo2);
    const float al = g.alpha;
    #pragma unroll
    for (int mf = 0; mf < 2; mf++) {
        const long long r0 = (long long)(by * BM + warpM * 32 + mf * 16 + (lane >> 2));
        const long long r1 = r0 + 8;
        #pragma unroll
        for (int nf = 0; nf < 8; nf++) {
            const int c0 = bx * BN + warpN * 64 + nf * 8 + (lane & 3) * 2;
            float v00 = acc[mf][nf][0] * al, v01 = acc[mf][nf][1] * al;
            float v10 = acc[mf][nf][2] * al, v11 = acc[mf][nf][3] * al;
            if (Chi) {
                __nv_bfloat16* ph0 = Chi + bz * g.sC + r0 * g.N + c0;
                __nv_bfloat16* pl0 = Clo + bz * g.sC + r0 * g.N + c0;
                __nv_bfloat16* ph1 = Chi + bz * g.sC + r1 * g.N + c0;
                __nv_bfloat16* pl1 = Clo + bz * g.sC + r1 * g.N + c0;
                __nv_bfloat16 h, l;
                __nv_bfloat162 hv, lv;
                split2(v00, h, l); hv.x = h; lv.x = l;
                split2(v01, h, l); hv.y = h; lv.y = l;
                *(__nv_bfloat162*)ph0 = hv; *(__nv_bfloat162*)pl0 = lv;
                split2(v10, h, l); hv.x = h; lv.x = l;
                split2(v11, h, l); hv.y = h; lv.y = l;
                *(__nv_bfloat162*)ph1 = hv; *(__nv_bfloat162*)pl1 = lv;
            } else {
                *(float2*)(Cf + bz * g.sC + r0 * g.N + c0) = make_float2(v00, v01);
                *(float2*)(Cf + bz * g.sC + r1 * g.N + c0) = make_float2(v10, v11);
            }
        }
    }
}

// ---------------- elementwise bf16 cast (hi only) ----------------
__global__ __launch_bounds__(256)
void splitH_kernel(const float* __restrict__ in, __nv_bfloat16* __restrict__ h, int n)
{
    int i = blockIdx.x * 256 + threadIdx.x;
    if (i < n) h[i] = __float2bfloat16(in[i]);
}

// ---------------- transpose + split: out[c][r] = in[r][c] ----------------
__global__ __launch_bounds__(256)
void transpose_split(const float* __restrict__ in, __nv_bfloat16* __restrict__ oh,
                     __nv_bfloat16* __restrict__ ol, int rows, int cols,
                     long long sIn, long long sOut)
{
    const int b = blockIdx.z;
    in += b * sIn; oh += b * sOut; ol += b * sOut;
    __shared__ float t[32][33];
    const int c0 = blockIdx.x * 32, r0 = blockIdx.y * 32;
    const int x = threadIdx.x & 31, y = threadIdx.x >> 5;  // 32x8
    #pragma unroll
    for (int r = y; r < 32; r += 8) t[r][x] = in[(long long)(r0 + r) * cols + c0 + x];
    __syncthreads();
    #pragma unroll
    for (int r = y; r < 32; r += 8) {
        __nv_bfloat16 h, l;
        split2(t[x][r], h, l);
        oh[(long long)(c0 + r) * rows + r0 + x] = h;
        ol[(long long)(c0 + r) * rows + r0 + x] = l;
    }
}

// merged 3-weight transpose (z selects q/k/v)
struct TW3 { const float *i0, *i1, *i2; __nv_bfloat16 *h0, *h1, *h2, *l0, *l1, *l2; };
__global__ __launch_bounds__(256)
void transpose_w3(TW3 a)
{
    const int z = blockIdx.z;
    const float* in = (z == 0 ? a.i0 : z == 1 ? a.i1 : a.i2);
    __nv_bfloat16* oh = (z == 0 ? a.h0 : z == 1 ? a.h1 : a.h2);
    __nv_bfloat16* ol = (z == 0 ? a.l0 : z == 1 ? a.l1 : a.l2);
    __shared__ float t[32][33];
    const int c0 = blockIdx.x * 32, r0 = blockIdx.y * 32;
    const int x = threadIdx.x & 31, y = threadIdx.x >> 5;
    #pragma unroll
    for (int r = y; r < 32; r += 8) t[r][x] = in[(long long)(r0 + r) * Dd + c0 + x];
    __syncthreads();
    #pragma unroll
    for (int r = y; r < 32; r += 8) {
        __nv_bfloat16 h, l;
        split2(t[x][r], h, l);
        oh[(long long)(c0 + r) * Dd + r0 + x] = h;
        ol[(long long)(c0 + r) * Dd + r0 + x] = l;
    }
}

// ---------------- positions + splat influence: 4 tokens / 256 threads ----------------
__global__ __launch_bounds__(256)
void pos_influence_kernel(const float* __restrict__ x, const float* __restrict__ posW,
                          const float* __restrict__ posB, const float* __restrict__ posBias,
                          const float* __restrict__ splatPos, const float* __restrict__ logScales,
                          float* __restrict__ wout)
{
    const int t0 = blockIdx.x * 4;           // first token of this block
    const int b = t0 >> 10;
    const int s0 = t0 & 1023;
    __shared__ float xs[4][Dd];
    __shared__ float pos[4][Ee];
    const int tid = threadIdx.x;
    const int e = tid & 63, tg = tid >> 6;   // (embed dim, token group)
    for (int i = tid; i < 4 * Dd; i += 256)
        xs[i >> 10][i & 1023] = x[(long long)t0 * Dd + i];
    __syncthreads();
    float acc = posB[e];
    const float* xr = xs[tg];
    #pragma unroll 8
    for (int d = 0; d < Dd; d++) acc += xr[d] * __ldg(&posW[d * Ee + e]);
    pos[tg][e] = tanhf(acc) + posBias[(s0 + tg) * Ee + e];
    __syncthreads();
    if (tid < 64) {
        const int n = tid & 15, tk = tid >> 4;
        float sc = expf(logScales[n]);
        sc = fminf(fmaxf(sc, 0.3f), 2.0f);
        float dsq = 0.0f;
        #pragma unroll
        for (int j = 0; j < Ee; j++) {
            float d = pos[tk][j] - splatPos[n * Ee + j];
            dsq += d * d;
        }
        float inf = fmaxf(__expf(-0.5f * dsq / (sc * sc)), 0.01f);
        wout[((long long)b * Nn + n) * Ss + s0 + tk] = inf;
    }
}

// ---------------- aggregated softmax -> P̄ (bf16 hi only) ----------------
__global__ __launch_bounds__(256)
void pbar_kernel(const float* __restrict__ Abuf, const float* __restrict__ wbuf,
                 const float* __restrict__ gates, __nv_bfloat16* __restrict__ Phi)
{
    const int row = blockIdx.x;
    const int b = row >> 10, i = row & 1023;
    const float* Arow = Abuf + ((long long)b << 20) + ((long long)i << 10);
    const int tid = threadIdx.x;
    const int len = i + 1;
    __shared__ float red[9];
    float aL[4], accL[4] = {0, 0, 0, 0};
    #pragma unroll
    for (int k = 0; k < 4; k++) {
        int j = tid + k * 256;
        aL[k] = (j < len) ? Arow[j] : 0.0f;
    }
    #pragma unroll 1
    for (int n = 0; n < Nn; n++) {
        const float* wrow = wbuf + (((long long)b * Nn + n) << 10);
        const float wi = wrow[i];
        float eL[4];
        float s = 0.0f;
        #pragma unroll
        for (int k = 0; k < 4; k++) {
            int j = tid + k * 256;
            if (j < len) {
                float e = __expf(wi * wrow[j] * aL[k]);  // |arg| small: no max shift needed
                eL[k] = e; s += e;
            } else eL[k] = 0.0f;
        }
        s = blockSum(s, red);
        const float gsc = (1.0f / (1.0f + __expf(-gates[n]))) / (16.0f * s);
        #pragma unroll
        for (int k = 0; k < 4; k++) accL[k] += gsc * eL[k];
    }
    __nv_bfloat16* ph = Phi + ((long long)b << 20) + ((long long)i << 10);
    #pragma unroll
    for (int k = 0; k < 4; k++) {
        int j = tid + k * 256;
        ph[j] = __float2bfloat16(accL[k]);
    }
}

// ---------------- residual + LayerNorm ----------------
__global__ __launch_bounds__(256)
void final_ln_kernel(const float* __restrict__ x, const float* __restrict__ comb,
                     const float* __restrict__ rwp, const float* __restrict__ lnw,
                     const float* __restrict__ lnb, float* __restrict__ out)
{
    const int row = blockIdx.x;
    const int tid = threadIdx.x;
    __shared__ float red[9];
    const float rw = 1.0f / (1.0f + expf(-rwp[0]));
    const float om = 1.0f - rw;
    const float4 xv = ((const float4*)(x + (long long)row * Dd))[tid];
    const float4 cv = ((const float4*)(comb + (long long)row * Dd))[tid];
    float o0 = rw * xv.x + om * cv.x;
    float o1 = rw * xv.y + om * cv.y;
    float o2 = rw * xv.z + om * cv.z;
    float o3 = rw * xv.w + om * cv.w;
    float s = o0 + o1 + o2 + o3;
    float sq = o0 * o0 + o1 * o1 + o2 * o2 + o3 * o3;
    s = blockSum(s, red);
    __syncthreads();
    sq = blockSum(sq, red);
    const float mean = s * (1.0f / Dd);
    const float var = sq * (1.0f / Dd) - mean * mean;
    const float rstd = rsqrtf(var + 1e-5f);
    const float4 wv = ((const float4*)lnw)[tid];
    const float4 bv = ((const float4*)lnb)[tid];
    float4 ov;
    ov.x = (o0 - mean) * rstd * wv.x + bv.x;
    ov.y = (o1 - mean) * rstd * wv.y + bv.y;
    ov.z = (o2 - mean) * rstd * wv.z + bv.z;
    ov.w = (o3 - mean) * rstd * wv.w + bv.w;
    ((float4*)(out + (long long)row * Dd))[tid] = ov;
}

// ---------------- host launcher ----------------
extern "C" void kernel_launch(void* const* d_in, const int* in_sizes, int n_in,
                              void* d_out, int out_size)
{
    const float* x        = (const float*)d_in[0];
    const float* posW     = (const float*)d_in[1];
    const float* posB     = (const float*)d_in[2];
    const float* posBias  = (const float*)d_in[3];
    const float* splatPos = (const float*)d_in[4];
    const float* logSc    = (const float*)d_in[5];
    const float* qW       = (const float*)d_in[6];
    const float* kW       = (const float*)d_in[7];
    const float* vW       = (const float*)d_in[8];
    const float* gates    = (const float*)d_in[9];
    const float* rwp      = (const float*)d_in[10];
    const float* lnw      = (const float*)d_in[11];
    const float* lnb      = (const float*)d_in[12];
    float* out = (float*)d_out;

    // one-time: raise dynamic-smem limits (first call is pre-capture)
    static bool inited = []() {
        cudaFuncSetAttribute(hmma_gemm<0, 2>, cudaFuncAttributeMaxDynamicSharedMemorySize, GSMEM);
        cudaFuncSetAttribute(hmma_gemm<1, 3>, cudaFuncAttributeMaxDynamicSharedMemorySize, GSMEM);
        cudaFuncSetAttribute(hmma_gemm<2, 2>, cudaFuncAttributeMaxDynamicSharedMemorySize, GSMEM);
        return true;
    }();
    (void)inited;

    float *A, *V, *comb, *w;
    __nv_bfloat16 *xh, *wqh, *wql, *wkh, *wkl, *wvh, *wvl;
    __nv_bfloat16 *Qh, *Ql, *Kh, *Kl, *Vth, *Vtl, *Ph;
    cudaGetSymbolAddress((void**)&A, g_A);
    cudaGetSymbolAddress((void**)&V, g_V);
    cudaGetSymbolAddress((void**)&comb, g_comb);
    cudaGetSymbolAddress((void**)&w, g_w);
    cudaGetSymbolAddress((void**)&xh, g_xh);
    cudaGetSymbolAddress((void**)&wqh, g_wqh); cudaGetSymbolAddress((void**)&wql, g_wql);
    cudaGetSymbolAddress((void**)&wkh, g_wkh); cudaGetSymbolAddress((void**)&wkl, g_wkl);
    cudaGetSymbolAddress((void**)&wvh, g_wvh); cudaGetSymbolAddress((void**)&wvl, g_wvl);
    cudaGetSymbolAddress((void**)&Qh, g_Qh);   cudaGetSymbolAddress((void**)&Ql, g_Ql);
    cudaGetSymbolAddress((void**)&Kh, g_Kh);   cudaGetSymbolAddress((void**)&Kl, g_Kl);
    cudaGetSymbolAddress((void**)&Vth, g_Vth); cudaGetSymbolAddress((void**)&Vtl, g_Vtl);
    cudaGetSymbolAddress((void**)&Ph, g_Ph);

    const float inv_sqrt_d = 1.0f / 32.0f;

    // prep: influence, x->bf16, W^T hi/lo splits
    pos_influence_kernel<<<Mtot / 4, 256>>>(x, posW, posB, posBias, splatPos, logSc, w);
    splitH_kernel<<<(Mtot * Dd) / 256, 256>>>(x, xh, Mtot * Dd);
    {
        TW3 tw = { qW, kW, vW, wqh, wkh, wvh, wql, wkl, wvl };
        transpose_w3<<<dim3(32, 32, 3), 256>>>(tw);
    }

    // QKV projections (2-pass): z = 0(Q,split) / 1(K,split) / 2(V,fp32)
    {
        GemmArgs a = {};
        a.Ahi = xh; a.Alo = xh; a.sA = 0;
        a.Bhi0 = wqh; a.Bhi1 = wkh; a.Bhi2 = wvh;
        a.Blo0 = wql; a.Blo1 = wkl; a.Blo2 = wvl; a.sB = 0;
        a.Cf2 = V;
        a.Chi0 = Qh; a.Chi1 = Kh; a.Clo0 = Ql; a.Clo1 = Kl; a.sC = 0;
        a.M = Mtot; a.N = Dd; a.K = Dd; a.alpha = 1.0f;
        hmma_gemm<0, 2><<<dim3(Dd / BN, Mtot / BM, 3), 256, GSMEM>>>(a);
    }
    // V^T split (per batch)
    transpose_split<<<dim3(32, 32, Bb), 256>>>(V, Vth, Vtl, Ss, Dd,
                                               (long long)Ss * Dd, (long long)Dd * Ss);
    // scores A = Q K^T / sqrt(d) (3-pass), lower-tri tiles only
    {
        GemmArgs a = {};
        a.Ahi = Qh; a.Alo = Ql; a.sA = (long long)Ss * Dd;
        a.Bhi0 = Kh; a.Bhi1 = Kh; a.Bhi2 = Kh;
        a.Blo0 = Kl; a.Blo1 = Kl; a.Blo2 = Kl; a.sB = (long long)Ss * Dd;
        a.Cf0 = A; a.Cf1 = A; a.Cf2 = A; a.sC = (long long)Ss * Ss;
        a.M = Ss; a.N = Ss; a.K = Dd; a.alpha = inv_sqrt_d;
        hmma_gemm<1, 3><<<dim3(Ss / BN, Ss / BM, Bb), 256, GSMEM>>>(a);
    }
    // aggregated softmax -> P̄ (bf16)
    pbar_kernel<<<Mtot, 256>>>(A, w, gates, Ph);
    // comb = P̄ @ V (2-pass: Ph*(Vh+Vl)), causal K-truncation
    {
        GemmArgs a = {};
        a.Ahi = Ph; a.Alo = Ph; a.sA = (long long)Ss * Ss;
        a.Bhi0 = Vth; a.Bhi1 = Vth; a.Bhi2 = Vth;
        a.Blo0 = Vtl; a.Blo1 = Vtl; a.Blo2 = Vtl; a.sB = (long long)Dd * Ss;
        a.Cf0 = comb; a.Cf1 = comb; a.Cf2 = comb; a.sC = (long long)Ss * Dd;
        a.M = Ss; a.N = Dd; a.K = Ss; a.alpha = 1.0f;
        hmma_gemm<2, 2><<<dim3(Dd / BN, Ss / BM, Bb), 256, GSMEM>>>(a);
    }
    // residual + LayerNorm
    final_ln_kernel<<<Mtot, 256>>>(x, comb, rwp, lnw, lnb, out);
}

// round 6
// speedup vs baseline: 4.9721x; 1.6127x over previous
#include <cuda_runtime.h>
#include <cuda_bf16.h>
#include <math.h>
#include <stdint.h>

#define Bb 2
#define Ss 1024
#define Dd 1024
#define Ee 64
#define Nn 16
#define Mtot (Bb * Ss)

// ---------------- scratch (no allocation allowed) ----------------
__device__ float g_A[Bb * Ss * Ss];        // QK^T/sqrt(d) fp32
__device__ float g_V[Bb * Ss * Dd];        // V fp32 (pre-transpose)
__device__ float g_comb[Bb * Ss * Dd];
__device__ float g_w[Bb * Nn * Ss];
__device__ __nv_bfloat16 g_xh[Mtot * Dd];
__device__ __nv_bfloat16 g_wqh[Dd * Dd];
__device__ __nv_bfloat16 g_wkh[Dd * Dd];
__device__ __nv_bfloat16 g_wvh[Dd * Dd];
__device__ __nv_bfloat16 g_Qh[Mtot * Dd];
__device__ __nv_bfloat16 g_Kh[Mtot * Dd];
__device__ __nv_bfloat16 g_Vth[Bb * Dd * Ss];
__device__ __nv_bfloat16 g_Ph[Bb * Ss * Ss];

// ---------------- helpers ----------------
__device__ __forceinline__ uint32_t smem_u32(const void* p) {
    uint32_t a;
    asm("{ .reg .u64 t; cvta.to.shared.u64 t, %1; cvt.u32.u64 %0, t; }" : "=r"(a) : "l"(p));
    return a;
}
// SW64 swizzle: 64B rows, XOR 16B-column bits [5:4] with row bits (off[8:7])
__device__ __forceinline__ uint32_t sw64(uint32_t off) { return off ^ ((off >> 3) & 0x30); }

#define CP_ASYNC16(s, g) \
    asm volatile("cp.async.cg.shared.global [%0], [%1], 16;" :: "r"(s), "l"(g) : "memory")
#define CP_COMMIT() asm volatile("cp.async.commit_group;" ::: "memory")
#define CP_WAIT2()  asm volatile("cp.async.wait_group 2;" ::: "memory")

#define LDSM_X4(r0, r1, r2, r3, addr) \
    asm volatile("ldmatrix.sync.aligned.m8n8.x4.shared.b16 {%0,%1,%2,%3}, [%4];" \
        : "=r"(r0), "=r"(r1), "=r"(r2), "=r"(r3) : "r"(addr) : "memory")

#define MMA16816(ac, a, b0, b1) \
    asm volatile("mma.sync.aligned.m16n8k16.row.col.f32.bf16.bf16.f32 " \
        "{%0,%1,%2,%3}, {%4,%5,%6,%7}, {%8,%9}, {%0,%1,%2,%3};" \
        : "+f"((ac)[0]), "+f"((ac)[1]), "+f"((ac)[2]), "+f"((ac)[3]) \
        : "r"((a)[0]), "r"((a)[1]), "r"((a)[2]), "r"((a)[3]), "r"(b0), "r"(b1))

// ---------------- reductions ----------------
__device__ __forceinline__ float warpSum(float v) {
    #pragma unroll
    for (int o = 16; o; o >>= 1) v += __shfl_xor_sync(0xffffffffu, v, o);
    return v;
}
__device__ __forceinline__ float blockSum(float v, float* red) {
    int lane = threadIdx.x & 31, w = threadIdx.x >> 5;
    v = warpSum(v);
    if (lane == 0) red[w] = v;
    __syncthreads();
    if (w == 0) {
        float t = (lane < 8) ? red[lane] : 0.0f;
        t = warpSum(t);
        if (lane == 0) red[8] = t;
    }
    __syncthreads();
    return red[8];
}

// ---------------- single-pass bf16 HMMA GEMM ----------------
// D[M,N] = alpha * A[M,K] @ B[N,K]^T
#define BM 128
#define BN 128
#define BKC 32            // bf16 K elems per chunk (64B rows)
#define STAGE_BYTES (128 * 32 * 2)
#define NSTAGE 4
#define GSMEM (2 * NSTAGE * STAGE_BYTES)   // 65536

struct GemmArgs {
    const __nv_bfloat16* A; long long sA;
    const __nv_bfloat16 *B0, *B1, *B2; long long sB;
    float *Cf0, *Cf1, *Cf2;
    __nv_bfloat16 *Cb0, *Cb1, *Cb2; long long sC;
    int M, N, K; float alpha;
};

// CAUSAL: 0=none, 1=skip tiles above diagonal (score), 2=K-truncate (PV)
template <int CAUSAL>
__global__ __launch_bounds__(256)
void hmma_gemm(GemmArgs g)
{
    const int bx = blockIdx.x, by = blockIdx.y, bz = blockIdx.z;
    if (CAUSAL == 1 && bx > by) return;
    int kEnd = g.K;
    if (CAUSAL == 2) kEnd = min(g.K, (by + 1) * BM);
    const int NC = kEnd / BKC;

    extern __shared__ __align__(128) char dsm[];
    const uint32_t sAb = smem_u32(dsm);
    const uint32_t sBb = sAb + NSTAGE * STAGE_BYTES;

    const int tid = threadIdx.x, wid = tid >> 5, lane = tid & 31;
    const int warpM = wid >> 1, warpN = wid & 1;

    const __nv_bfloat16* Ah = g.A + bz * g.sA;
    const __nv_bfloat16* Bh = (bz == 0 ? g.B0 : bz == 1 ? g.B1 : g.B2) + bz * g.sB;

    float acc[2][8][4];
    #pragma unroll
    for (int i = 0; i < 2; i++)
        #pragma unroll
        for (int j = 0; j < 8; j++)
            #pragma unroll
            for (int k = 0; k < 4; k++) acc[i][j][k] = 0.0f;

    // per-thread load mapping: 512 x 16B units per tile, 2 per thread
    const int ldRow0 = tid >> 2;
    const int ldC0   = (tid & 3) * 16;
    const int ldRow1 = (tid + 256) >> 2;
    const int ldC1   = ldC0;

    const __nv_bfloat16* Arow = Ah + (long long)(by * BM) * g.K;
    const __nv_bfloat16* Brow = Bh + (long long)(bx * BN) * g.K;

    auto issue = [&](int it, int buf) {
        const int k0 = it * BKC;
        const uint32_t aB = sAb + buf * STAGE_BYTES;
        const uint32_t bB = sBb + buf * STAGE_BYTES;
        CP_ASYNC16(aB + sw64(ldRow0 * 64 + ldC0), Arow + (long long)ldRow0 * g.K + k0 + (ldC0 >> 1));
        CP_ASYNC16(aB + sw64(ldRow1 * 64 + ldC1), Arow + (long long)ldRow1 * g.K + k0 + (ldC1 >> 1));
        CP_ASYNC16(bB + sw64(ldRow0 * 64 + ldC0), Brow + (long long)ldRow0 * g.K + k0 + (ldC0 >> 1));
        CP_ASYNC16(bB + sw64(ldRow1 * 64 + ldC1), Brow + (long long)ldRow1 * g.K + k0 + (ldC1 >> 1));
    };

    // prologue: 3 stages in flight
    #pragma unroll
    for (int it = 0; it < 3; it++) {
        if (it < NC) issue(it, it);
        CP_COMMIT();
    }

    const int aRowL = (lane & 15);
    const int aHiK  = (lane >> 4);
    const int bRowL = ((lane & 16) >> 1) + (lane & 7);
    const int bHiK  = ((lane >> 3) & 1);

    #pragma unroll 1
    for (int it = 0; it < NC; it++) {
        CP_WAIT2();
        __syncthreads();
        // issue next chunk into buf (it+3)%4 == buf read at it-1; safe past the barrier
        const int nx = it + 3;
        if (nx < NC) issue(nx, nx & 3);
        CP_COMMIT();
        const int buf = it & 3;
        const uint32_t aB = sAb + buf * STAGE_BYTES;
        const uint32_t bB = sBb + buf * STAGE_BYTES;
        #pragma unroll
        for (int s = 0; s < 2; s++) {
            uint32_t ra[2][4], rb[4][4];
            #pragma unroll
            for (int mf = 0; mf < 2; mf++) {
                int row = warpM * 32 + mf * 16 + aRowL;
                int c16 = s * 2 + aHiK;
                uint32_t ad = aB + sw64(row * 64 + c16 * 16);
                LDSM_X4(ra[mf][0], ra[mf][1], ra[mf][2], ra[mf][3], ad);
            }
            #pragma unroll
            for (int ng = 0; ng < 4; ng++) {
                int nrow = warpN * 64 + ng * 16 + bRowL;
                int c16 = s * 2 + bHiK;
                uint32_t bd = bB + sw64(nrow * 64 + c16 * 16);
                LDSM_X4(rb[ng][0], rb[ng][1], rb[ng][2], rb[ng][3], bd);
            }
            #pragma unroll
            for (int mf = 0; mf < 2; mf++)
                #pragma unroll
                for (int ng = 0; ng < 4; ng++) {
                    MMA16816(acc[mf][ng * 2 + 0], ra[mf], rb[ng][0], rb[ng][1]);
                    MMA16816(acc[mf][ng * 2 + 1], ra[mf], rb[ng][2], rb[ng][3]);
                }
        }
    }

    // ---------------- epilogue ----------------
    float* Cf = (bz == 0 ? g.Cf0 : bz == 1 ? g.Cf1 : g.Cf2);
    __nv_bfloat16* Cb = (bz == 0 ? g.Cb0 : bz == 1 ? g.Cb1 : g.Cb2);
    const float al = g.alpha;
    #pragma unroll
    for (int mf = 0; mf < 2; mf++) {
        const long long r0 = (long long)(by * BM + warpM * 32 + mf * 16 + (lane >> 2));
        const long long r1 = r0 + 8;
        #pragma unroll
        for (int nf = 0; nf < 8; nf++) {
            const int c0 = bx * BN + warpN * 64 + nf * 8 + (lane & 3) * 2;
            float v00 = acc[mf][nf][0] * al, v01 = acc[mf][nf][1] * al;
            float v10 = acc[mf][nf][2] * al, v11 = acc[mf][nf][3] * al;
            if (Cb) {
                __nv_bfloat162 p0, p1;
                p0.x = __float2bfloat16(v00); p0.y = __float2bfloat16(v01);
                p1.x = __float2bfloat16(v10); p1.y = __float2bfloat16(v11);
                *(__nv_bfloat162*)(Cb + bz * g.sC + r0 * g.N + c0) = p0;
                *(__nv_bfloat162*)(Cb + bz * g.sC + r1 * g.N + c0) = p1;
            } else {
                *(float2*)(Cf + bz * g.sC + r0 * g.N + c0) = make_float2(v00, v01);
                *(float2*)(Cf + bz * g.sC + r1 * g.N + c0) = make_float2(v10, v11);
            }
        }
    }
}

// ---------------- elementwise bf16 cast ----------------
__global__ __launch_bounds__(256)
void splitH_kernel(const float* __restrict__ in, __nv_bfloat16* __restrict__ h, int n)
{
    int i = blockIdx.x * 256 + threadIdx.x;
    if (i < n) h[i] = __float2bfloat16(in[i]);
}

// ---------------- transpose to bf16: out[c][r] = bf16(in[r][c]) ----------------
__global__ __launch_bounds__(256)
void transpose_h(const float* __restrict__ in, __nv_bfloat16* __restrict__ oh,
                 int rows, int cols, long long sIn, long long sOut)
{
    const int b = blockIdx.z;
    in += b * sIn; oh += b * sOut;
    __shared__ float t[32][33];
    const int c0 = blockIdx.x * 32, r0 = blockIdx.y * 32;
    const int x = threadIdx.x & 31, y = threadIdx.x >> 5;  // 32x8
    #pragma unroll
    for (int r = y; r < 32; r += 8) t[r][x] = in[(long long)(r0 + r) * cols + c0 + x];
    __syncthreads();
    #pragma unroll
    for (int r = y; r < 32; r += 8)
        oh[(long long)(c0 + r) * rows + r0 + x] = __float2bfloat16(t[x][r]);
}

// merged 3-weight transpose (z selects q/k/v), hi only
struct TW3 { const float *i0, *i1, *i2; __nv_bfloat16 *h0, *h1, *h2; };
__global__ __launch_bounds__(256)
void transpose_w3(TW3 a)
{
    const int z = blockIdx.z;
    const float* in = (z == 0 ? a.i0 : z == 1 ? a.i1 : a.i2);
    __nv_bfloat16* oh = (z == 0 ? a.h0 : z == 1 ? a.h1 : a.h2);
    __shared__ float t[32][33];
    const int c0 = blockIdx.x * 32, r0 = blockIdx.y * 32;
    const int x = threadIdx.x & 31, y = threadIdx.x >> 5;
    #pragma unroll
    for (int r = y; r < 32; r += 8) t[r][x] = in[(long long)(r0 + r) * Dd + c0 + x];
    __syncthreads();
    #pragma unroll
    for (int r = y; r < 32; r += 8)
        oh[(long long)(c0 + r) * Dd + r0 + x] = __float2bfloat16(t[x][r]);
}

// ---------------- positions + splat influence: 4 tokens / 256 threads ----------------
__global__ __launch_bounds__(256)
void pos_influence_kernel(const float* __restrict__ x, const float* __restrict__ posW,
                          const float* __restrict__ posB, const float* __restrict__ posBias,
                          const float* __restrict__ splatPos, const float* __restrict__ logScales,
                          float* __restrict__ wout)
{
    const int t0 = blockIdx.x * 4;           // first token of this block
    const int b = t0 >> 10;
    const int s0 = t0 & 1023;
    __shared__ float xs[4][Dd];
    __shared__ float pos[4][Ee];
    const int tid = threadIdx.x;
    const int e = tid & 63, tg = tid >> 6;   // (embed dim, token group)
    for (int i = tid; i < 4 * Dd; i += 256)
        xs[i >> 10][i & 1023] = x[(long long)t0 * Dd + i];
    __syncthreads();
    float acc = posB[e];
    const float* xr = xs[tg];
    #pragma unroll 8
    for (int d = 0; d < Dd; d++) acc += xr[d] * __ldg(&posW[d * Ee + e]);
    pos[tg][e] = tanhf(acc) + posBias[(s0 + tg) * Ee + e];
    __syncthreads();
    if (tid < 64) {
        const int n = tid & 15, tk = tid >> 4;
        float sc = expf(logScales[n]);
        sc = fminf(fmaxf(sc, 0.3f), 2.0f);
        float dsq = 0.0f;
        #pragma unroll
        for (int j = 0; j < Ee; j++) {
            float d = pos[tk][j] - splatPos[n * Ee + j];
            dsq += d * d;
        }
        float inf = fmaxf(__expf(-0.5f * dsq / (sc * sc)), 0.01f);
        wout[((long long)b * Nn + n) * Ss + s0 + tk] = inf;
    }
}

// ---------------- aggregated softmax -> P̄ (bf16) ----------------
__global__ __launch_bounds__(256)
void pbar_kernel(const float* __restrict__ Abuf, const float* __restrict__ wbuf,
                 const float* __restrict__ gates, __nv_bfloat16* __restrict__ Phi)
{
    const int row = blockIdx.x;
    const int b = row >> 10, i = row & 1023;
    const float* Arow = Abuf + ((long long)b << 20) + ((long long)i << 10);
    const int tid = threadIdx.x;
    const int len = i + 1;
    __shared__ float red[9];
    float aL[4], accL[4] = {0, 0, 0, 0};
    #pragma unroll
    for (int k = 0; k < 4; k++) {
        int j = tid + k * 256;
        aL[k] = (j < len) ? Arow[j] : 0.0f;
    }
    #pragma unroll 1
    for (int n = 0; n < Nn; n++) {
        const float* wrow = wbuf + (((long long)b * Nn + n) << 10);
        const float wi = wrow[i];
        float eL[4];
        float s = 0.0f;
        #pragma unroll
        for (int k = 0; k < 4; k++) {
            int j = tid + k * 256;
            if (j < len) {
                float e = __expf(wi * wrow[j] * aL[k]);  // |arg| small: no max shift needed
                eL[k] = e; s += e;
            } else eL[k] = 0.0f;
        }
        s = blockSum(s, red);
        const float gsc = (1.0f / (1.0f + __expf(-gates[n]))) / (16.0f * s);
        #pragma unroll
        for (int k = 0; k < 4; k++) accL[k] += gsc * eL[k];
    }
    __nv_bfloat16* ph = Phi + ((long long)b << 20) + ((long long)i << 10);
    #pragma unroll
    for (int k = 0; k < 4; k++) {
        int j = tid + k * 256;
        ph[j] = __float2bfloat16(accL[k]);
    }
}

// ---------------- residual + LayerNorm ----------------
__global__ __launch_bounds__(256)
void final_ln_kernel(const float* __restrict__ x, const float* __restrict__ comb,
                     const float* __restrict__ rwp, const float* __restrict__ lnw,
                     const float* __restrict__ lnb, float* __restrict__ out)
{
    const int row = blockIdx.x;
    const int tid = threadIdx.x;
    __shared__ float red[9];
    const float rw = 1.0f / (1.0f + expf(-rwp[0]));
    const float om = 1.0f - rw;
    const float4 xv = ((const float4*)(x + (long long)row * Dd))[tid];
    const float4 cv = ((const float4*)(comb + (long long)row * Dd))[tid];
    float o0 = rw * xv.x + om * cv.x;
    float o1 = rw * xv.y + om * cv.y;
    float o2 = rw * xv.z + om * cv.z;
    float o3 = rw * xv.w + om * cv.w;
    float s = o0 + o1 + o2 + o3;
    float sq = o0 * o0 + o1 * o1 + o2 * o2 + o3 * o3;
    s = blockSum(s, red);
    __syncthreads();
    sq = blockSum(sq, red);
    const float mean = s * (1.0f / Dd);
    const float var = sq * (1.0f / Dd) - mean * mean;
    const float rstd = rsqrtf(var + 1e-5f);
    const float4 wv = ((const float4*)lnw)[tid];
    const float4 bv = ((const float4*)lnb)[tid];
    float4 ov;
    ov.x = (o0 - mean) * rstd * wv.x + bv.x;
    ov.y = (o1 - mean) * rstd * wv.y + bv.y;
    ov.z = (o2 - mean) * rstd * wv.z + bv.z;
    ov.w = (o3 - mean) * rstd * wv.w + bv.w;
    ((float4*)(out + (long long)row * Dd))[tid] = ov;
}

// ---------------- host launcher ----------------
extern "C" void kernel_launch(void* const* d_in, const int* in_sizes, int n_in,
                              void* d_out, int out_size)
{
    const float* x        = (const float*)d_in[0];
    const float* posW     = (const float*)d_in[1];
    const float* posB     = (const float*)d_in[2];
    const float* posBias  = (const float*)d_in[3];
    const float* splatPos = (const float*)d_in[4];
    const float* logSc    = (const float*)d_in[5];
    const float* qW       = (const float*)d_in[6];
    const float* kW       = (const float*)d_in[7];
    const float* vW       = (const float*)d_in[8];
    const float* gates    = (const float*)d_in[9];
    const float* rwp      = (const float*)d_in[10];
    const float* lnw      = (const float*)d_in[11];
    const float* lnb      = (const float*)d_in[12];
    float* out = (float*)d_out;

    // one-time: raise dynamic-smem limits (first call is pre-capture)
    static bool inited = []() {
        cudaFuncSetAttribute(hmma_gemm<0>, cudaFuncAttributeMaxDynamicSharedMemorySize, GSMEM);
        cudaFuncSetAttribute(hmma_gemm<1>, cudaFuncAttributeMaxDynamicSharedMemorySize, GSMEM);
        cudaFuncSetAttribute(hmma_gemm<2>, cudaFuncAttributeMaxDynamicSharedMemorySize, GSMEM);
        return true;
    }();
    (void)inited;

    float *A, *V, *comb, *w;
    __nv_bfloat16 *xh, *wqh, *wkh, *wvh, *Qh, *Kh, *Vth, *Ph;
    cudaGetSymbolAddress((void**)&A, g_A);
    cudaGetSymbolAddress((void**)&V, g_V);
    cudaGetSymbolAddress((void**)&comb, g_comb);
    cudaGetSymbolAddress((void**)&w, g_w);
    cudaGetSymbolAddress((void**)&xh, g_xh);
    cudaGetSymbolAddress((void**)&wqh, g_wqh);
    cudaGetSymbolAddress((void**)&wkh, g_wkh);
    cudaGetSymbolAddress((void**)&wvh, g_wvh);
    cudaGetSymbolAddress((void**)&Qh, g_Qh);
    cudaGetSymbolAddress((void**)&Kh, g_Kh);
    cudaGetSymbolAddress((void**)&Vth, g_Vth);
    cudaGetSymbolAddress((void**)&Ph, g_Ph);

    const float inv_sqrt_d = 1.0f / 32.0f;

    // prep: influence, x->bf16, W^T bf16
    pos_influence_kernel<<<Mtot / 4, 256>>>(x, posW, posB, posBias, splatPos, logSc, w);
    splitH_kernel<<<(Mtot * Dd) / 256, 256>>>(x, xh, Mtot * Dd);
    {
        TW3 tw = { qW, kW, vW, wqh, wkh, wvh };
        transpose_w3<<<dim3(32, 32, 3), 256>>>(tw);
    }

    // QKV projections (single pass): z = 0(Q) / 1(K) / 2(V fp32)
    {
        GemmArgs a = {};
        a.A = xh; a.sA = 0;
        a.B0 = wqh; a.B1 = wkh; a.B2 = wvh; a.sB = 0;
        a.Cf2 = V;
        a.Cb0 = Qh; a.Cb1 = Kh; a.sC = 0;
        a.M = Mtot; a.N = Dd; a.K = Dd; a.alpha = 1.0f;
        hmma_gemm<0><<<dim3(Dd / BN, Mtot / BM, 3), 256, GSMEM>>>(a);
    }
    // V^T -> bf16 (per batch)
    transpose_h<<<dim3(32, 32, Bb), 256>>>(V, Vth, Ss, Dd,
                                           (long long)Ss * Dd, (long long)Dd * Ss);
    // scores A = Q K^T / sqrt(d), lower-tri tiles only
    {
        GemmArgs a = {};
        a.A = Qh; a.sA = (long long)Ss * Dd;
        a.B0 = Kh; a.B1 = Kh; a.B2 = Kh; a.sB = (long long)Ss * Dd;
        a.Cf0 = A; a.Cf1 = A; a.Cf2 = A; a.sC = (long long)Ss * Ss;
        a.M = Ss; a.N = Ss; a.K = Dd; a.alpha = inv_sqrt_d;
        hmma_gemm<1><<<dim3(Ss / BN, Ss / BM, Bb), 256, GSMEM>>>(a);
    }
    // aggregated softmax -> P̄ (bf16)
    pbar_kernel<<<Mtot, 256>>>(A, w, gates, Ph);
    // comb = P̄ @ V (B = V^T [D,S]), causal K-truncation
    {
        GemmArgs a = {};
        a.A = Ph; a.sA = (long long)Ss * Ss;
        a.B0 = Vth; a.B1 = Vth; a.B2 = Vth; a.sB = (long long)Dd * Ss;
        a.Cf0 = comb; a.Cf1 = comb; a.Cf2 = comb; a.sC = (long long)Ss * Dd;
        a.M = Ss; a.N = Dd; a.K = Ss; a.alpha = 1.0f;
        hmma_gemm<2><<<dim3(Dd / BN, Ss / BM, Bb), 256, GSMEM>>>(a);
    }
    // residual + LayerNorm
    final_ln_kernel<<<Mtot, 256>>>(x, comb, rwp, lnw, lnb, out);
}

// round 7
// speedup vs baseline: 6.0154x; 1.2098x over previous
#include <cuda_runtime.h>
#include <cuda_bf16.h>
#include <math.h>
#include <stdint.h>

#define Bb 2
#define Ss 1024
#define Dd 1024
#define Ee 64
#define Nn 16
#define Mtot (Bb * Ss)

// ---------------- scratch (no allocation allowed) ----------------
__device__ float g_A[Bb * Ss * Ss];        // QK^T/sqrt(d) fp32
__device__ float g_comb[Bb * Ss * Dd];
__device__ float g_w[Bb * Nn * Ss];
__device__ __nv_bfloat16 g_xh[Mtot * Dd];
__device__ __nv_bfloat16 g_wqh[Dd * Dd];
__device__ __nv_bfloat16 g_wkh[Dd * Dd];
__device__ __nv_bfloat16 g_wvh[Dd * Dd];
__device__ __nv_bfloat16 g_Qh[Mtot * Dd];
__device__ __nv_bfloat16 g_Kh[Mtot * Dd];
__device__ __nv_bfloat16 g_Vth[Bb * Dd * Ss];   // V^T bf16, [b][d][s]
__device__ __nv_bfloat16 g_Ph[Bb * Ss * Ss];

// ---------------- helpers ----------------
__device__ __forceinline__ uint32_t smem_u32(const void* p) {
    uint32_t a;
    asm("{ .reg .u64 t; cvta.to.shared.u64 t, %1; cvt.u32.u64 %0, t; }" : "=r"(a) : "l"(p));
    return a;
}
// SW128 swizzle for 128B rows: 16B-col bits [4:7) ^= row bits (off bits [7:10))
__device__ __forceinline__ uint32_t sw128(uint32_t off) { return off ^ ((off >> 3) & 0x70); }

#define CP_ASYNC16(s, g) \
    asm volatile("cp.async.cg.shared.global [%0], [%1], 16;" :: "r"(s), "l"(g) : "memory")
#define CP_COMMIT() asm volatile("cp.async.commit_group;" ::: "memory")
#define CP_WAIT1()  asm volatile("cp.async.wait_group 1;" ::: "memory")

#define LDSM_X4(r0, r1, r2, r3, addr) \
    asm volatile("ldmatrix.sync.aligned.m8n8.x4.shared.b16 {%0,%1,%2,%3}, [%4];" \
        : "=r"(r0), "=r"(r1), "=r"(r2), "=r"(r3) : "r"(addr) : "memory")

#define MMA16816(ac, a, b0, b1) \
    asm volatile("mma.sync.aligned.m16n8k16.row.col.f32.bf16.bf16.f32 " \
        "{%0,%1,%2,%3}, {%4,%5,%6,%7}, {%8,%9}, {%0,%1,%2,%3};" \
        : "+f"((ac)[0]), "+f"((ac)[1]), "+f"((ac)[2]), "+f"((ac)[3]) \
        : "r"((a)[0]), "r"((a)[1]), "r"((a)[2]), "r"((a)[3]), "r"(b0), "r"(b1))

// ---------------- reductions ----------------
__device__ __forceinline__ float warpSum(float v) {
    #pragma unroll
    for (int o = 16; o; o >>= 1) v += __shfl_xor_sync(0xffffffffu, v, o);
    return v;
}
__device__ __forceinline__ float blockSum(float v, float* red) {
    int lane = threadIdx.x & 31, w = threadIdx.x >> 5;
    v = warpSum(v);
    if (lane == 0) red[w] = v;
    __syncthreads();
    if (w == 0) {
        float t = (lane < 8) ? red[lane] : 0.0f;
        t = warpSum(t);
        if (lane == 0) red[8] = t;
    }
    __syncthreads();
    return red[8];
}

// ---------------- single-pass bf16 HMMA GEMM ----------------
// D[M,N] = alpha * A[M,K] @ B[N,K]^T
#define BM 128
#define BN 128
#define BKC 64            // bf16 K elems per chunk (128B rows, SW128)
#define STAGE_BYTES (128 * 64 * 2)   // 16KB per tensor per stage
#define NSTAGE 3
#define GSMEM (2 * NSTAGE * STAGE_BYTES)   // 98304

struct GemmArgs {
    const __nv_bfloat16* A; long long sA;
    const __nv_bfloat16 *B0, *B1, *B2; long long sB;
    float* Cf;                       // fp32 out (score/PV)
    __nv_bfloat16 *Cb0, *Cb1;        // bf16 out (Q,K)
    __nv_bfloat16* Vt;               // transposed bf16 out (V, z==2)
    long long sC;
    int M, N, K; float alpha;
};

// CAUSAL: 0=QKV (z2 -> transposed V epilogue), 1=score (skip upper tiles), 2=PV (K-truncate)
template <int CAUSAL>
__global__ __launch_bounds__(256)
void hmma_gemm(GemmArgs g)
{
    const int bx = blockIdx.x, by = blockIdx.y, bz = blockIdx.z;
    if (CAUSAL == 1 && bx > by) return;
    int kEnd = g.K;
    if (CAUSAL == 2) kEnd = min(g.K, (by + 1) * BM);
    const int NC = kEnd / BKC;

    extern __shared__ __align__(128) char dsm[];
    const uint32_t sAb = smem_u32(dsm);
    const uint32_t sBb = sAb + NSTAGE * STAGE_BYTES;

    const int tid = threadIdx.x, wid = tid >> 5, lane = tid & 31;
    const int warpM = wid >> 1, warpN = wid & 1;

    const __nv_bfloat16* Ah = g.A + bz * g.sA;
    const __nv_bfloat16* Bh = (bz == 0 ? g.B0 : bz == 1 ? g.B1 : g.B2) + bz * g.sB;

    float acc[2][8][4];
    #pragma unroll
    for (int i = 0; i < 2; i++)
        #pragma unroll
        for (int j = 0; j < 8; j++)
            #pragma unroll
            for (int k = 0; k < 4; k++) acc[i][j][k] = 0.0f;

    // cp.async mapping: tile = 128 rows x 8 16B-units; 4 units per tensor per thread
    const int lc16 = tid & 7;          // 16B col within 128B row
    const int lrow = tid >> 3;         // 0..31 (+32 per r)

    const __nv_bfloat16* Arow = Ah + (long long)(by * BM) * g.K;
    const __nv_bfloat16* Brow = Bh + (long long)(bx * BN) * g.K;
    const int Kld = g.K;

    auto issue = [&](int it, int buf) {
        const int k0 = it * BKC;
        const uint32_t aB = sAb + buf * STAGE_BYTES;
        const uint32_t bB = sBb + buf * STAGE_BYTES;
        #pragma unroll
        for (int r = 0; r < 4; r++) {
            const int row = lrow + 32 * r;
            const uint32_t off = sw128(row * 128 + lc16 * 16);
            const long long goff = (long long)row * Kld + k0 + lc16 * 8;
            CP_ASYNC16(aB + off, Arow + goff);
            CP_ASYNC16(bB + off, Brow + goff);
        }
    };

    // prologue: 2 stages in flight
    issue(0, 0); CP_COMMIT();
    if (NC > 1) issue(1, 1);
    CP_COMMIT();

    const int aRowL = (lane & 15);
    const int aHiK  = (lane >> 4);
    const int bRowL = ((lane & 16) >> 1) + (lane & 7);
    const int bHiK  = ((lane >> 3) & 1);

    #pragma unroll 1
    for (int it = 0; it < NC; it++) {
        CP_WAIT1();
        __syncthreads();
        const int nx = it + 2;
        if (nx < NC) issue(nx, nx % 3);
        CP_COMMIT();
        const int buf = it % 3;
        const uint32_t aB = sAb + buf * STAGE_BYTES;
        const uint32_t bB = sBb + buf * STAGE_BYTES;
        #pragma unroll
        for (int s = 0; s < 4; s++) {
            uint32_t ra[2][4], rb[4][4];
            #pragma unroll
            for (int mf = 0; mf < 2; mf++) {
                int row = warpM * 32 + mf * 16 + aRowL;
                int c16 = s * 2 + aHiK;
                uint32_t ad = aB + sw128(row * 128 + c16 * 16);
                LDSM_X4(ra[mf][0], ra[mf][1], ra[mf][2], ra[mf][3], ad);
            }
            #pragma unroll
            for (int ng = 0; ng < 4; ng++) {
                int nrow = warpN * 64 + ng * 16 + bRowL;
                int c16 = s * 2 + bHiK;
                uint32_t bd = bB + sw128(nrow * 128 + c16 * 16);
                LDSM_X4(rb[ng][0], rb[ng][1], rb[ng][2], rb[ng][3], bd);
            }
            #pragma unroll
            for (int mf = 0; mf < 2; mf++)
                #pragma unroll
                for (int ng = 0; ng < 4; ng++) {
                    MMA16816(acc[mf][ng * 2 + 0], ra[mf], rb[ng][0], rb[ng][1]);
                    MMA16816(acc[mf][ng * 2 + 1], ra[mf], rb[ng][2], rb[ng][3]);
                }
        }
    }

    const float al = g.alpha;

    if (CAUSAL == 0 && bz == 2) {
        // ---------- V epilogue: transpose via smem, write bf16 V^T ----------
        __nv_bfloat16 (*st)[136] = (__nv_bfloat16 (*)[136])dsm;
        __syncthreads();
        #pragma unroll
        for (int mf = 0; mf < 2; mf++) {
            const int r_l = warpM * 32 + mf * 16 + (lane >> 2);
            #pragma unroll
            for (int nf = 0; nf < 8; nf++) {
                const int c_l = warpN * 64 + nf * 8 + (lane & 3) * 2;
                st[c_l][r_l]         = __float2bfloat16(acc[mf][nf][0]);
                st[c_l + 1][r_l]     = __float2bfloat16(acc[mf][nf][1]);
                st[c_l][r_l + 8]     = __float2bfloat16(acc[mf][nf][2]);
                st[c_l + 1][r_l + 8] = __float2bfloat16(acc[mf][nf][3]);
            }
        }
        __syncthreads();
        const int rb_ = by >> 3;             // batch
        const int s0 = (by & 7) * 128;       // seq offset within batch
        const int d = tid >> 1;              // local feature row
        const int so = (tid & 1) * 64;       // half-row of 128 s elems
        const uint4* src = (const uint4*)&st[d][so];
        uint4* dst = (uint4*)(g.Vt + (long long)rb_ * Dd * Ss
                              + (long long)(bx * BN + d) * Ss + s0 + so);
        #pragma unroll
        for (int i = 0; i < 8; i++) dst[i] = src[i];
        return;
    }

    // ---------------- standard epilogue ----------------
    __nv_bfloat16* Cb = (CAUSAL == 0) ? (bz == 0 ? g.Cb0 : g.Cb1) : nullptr;
    float* Cf = g.Cf;
    #pragma unroll
    for (int mf = 0; mf < 2; mf++) {
        const long long r0 = (long long)(by * BM + warpM * 32 + mf * 16 + (lane >> 2));
        const long long r1 = r0 + 8;
        #pragma unroll
        for (int nf = 0; nf < 8; nf++) {
            const int c0 = bx * BN + warpN * 64 + nf * 8 + (lane & 3) * 2;
            float v00 = acc[mf][nf][0] * al, v01 = acc[mf][nf][1] * al;
            float v10 = acc[mf][nf][2] * al, v11 = acc[mf][nf][3] * al;
            if (CAUSAL == 0) {
                __nv_bfloat162 p0, p1;
                p0.x = __float2bfloat16(v00); p0.y = __float2bfloat16(v01);
                p1.x = __float2bfloat16(v10); p1.y = __float2bfloat16(v11);
                *(__nv_bfloat162*)(Cb + bz * g.sC + r0 * g.N + c0) = p0;
                *(__nv_bfloat162*)(Cb + bz * g.sC + r1 * g.N + c0) = p1;
            } else {
                *(float2*)(Cf + bz * g.sC + r0 * g.N + c0) = make_float2(v00, v01);
                *(float2*)(Cf + bz * g.sC + r1 * g.N + c0) = make_float2(v10, v11);
            }
        }
    }
}

// ---------------- elementwise bf16 cast ----------------
__global__ __launch_bounds__(256)
void splitH_kernel(const float* __restrict__ in, __nv_bfloat16* __restrict__ h, int n)
{
    int i = blockIdx.x * 256 + threadIdx.x;
    if (i < n) h[i] = __float2bfloat16(in[i]);
}

// merged 3-weight transpose (z selects q/k/v), bf16 out
struct TW3 { const float *i0, *i1, *i2; __nv_bfloat16 *h0, *h1, *h2; };
__global__ __launch_bounds__(256)
void transpose_w3(TW3 a)
{
    const int z = blockIdx.z;
    const float* in = (z == 0 ? a.i0 : z == 1 ? a.i1 : a.i2);
    __nv_bfloat16* oh = (z == 0 ? a.h0 : z == 1 ? a.h1 : a.h2);
    __shared__ float t[32][33];
    const int c0 = blockIdx.x * 32, r0 = blockIdx.y * 32;
    const int x = threadIdx.x & 31, y = threadIdx.x >> 5;
    #pragma unroll
    for (int r = y; r < 32; r += 8) t[r][x] = in[(long long)(r0 + r) * Dd + c0 + x];
    __syncthreads();
    #pragma unroll
    for (int r = y; r < 32; r += 8)
        oh[(long long)(c0 + r) * Dd + r0 + x] = __float2bfloat16(t[x][r]);
}

// ---------------- positions + splat influence: 4 tokens / 256 threads ----------------
__global__ __launch_bounds__(256)
void pos_influence_kernel(const float* __restrict__ x, const float* __restrict__ posW,
                          const float* __restrict__ posB, const float* __restrict__ posBias,
                          const float* __restrict__ splatPos, const float* __restrict__ logScales,
                          float* __restrict__ wout)
{
    const int t0 = blockIdx.x * 4;
    const int b = t0 >> 10;
    const int s0 = t0 & 1023;
    __shared__ float xs[4][Dd];
    __shared__ float pos[4][Ee];
    const int tid = threadIdx.x;
    const int e = tid & 63, tg = tid >> 6;
    for (int i = tid; i < 4 * Dd; i += 256)
        xs[i >> 10][i & 1023] = x[(long long)t0 * Dd + i];
    __syncthreads();
    float acc = posB[e];
    const float* xr = xs[tg];
    #pragma unroll 8
    for (int d = 0; d < Dd; d++) acc += xr[d] * __ldg(&posW[d * Ee + e]);
    pos[tg][e] = tanhf(acc) + posBias[(s0 + tg) * Ee + e];
    __syncthreads();
    if (tid < 64) {
        const int n = tid & 15, tk = tid >> 4;
        float sc = expf(logScales[n]);
        sc = fminf(fmaxf(sc, 0.3f), 2.0f);
        float dsq = 0.0f;
        #pragma unroll
        for (int j = 0; j < Ee; j++) {
            float d = pos[tk][j] - splatPos[n * Ee + j];
            dsq += d * d;
        }
        float inf = fmaxf(__expf(-0.5f * dsq / (sc * sc)), 0.01f);
        wout[((long long)b * Nn + n) * Ss + s0 + tk] = inf;
    }
}

// ---------------- aggregated softmax -> P̄ (bf16) ----------------
__global__ __launch_bounds__(256)
void pbar_kernel(const float* __restrict__ Abuf, const float* __restrict__ wbuf,
                 const float* __restrict__ gates, __nv_bfloat16* __restrict__ Phi)
{
    const int row = blockIdx.x;
    const int b = row >> 10, i = row & 1023;
    const float* Arow = Abuf + ((long long)b << 20) + ((long long)i << 10);
    const int tid = threadIdx.x;
    const int len = i + 1;
    __shared__ float red[9];
    float aL[4], accL[4] = {0, 0, 0, 0};
    #pragma unroll
    for (int k = 0; k < 4; k++) {
        int j = tid + k * 256;
        aL[k] = (j < len) ? Arow[j] : 0.0f;
    }
    #pragma unroll 1
    for (int n = 0; n < Nn; n++) {
        const float* wrow = wbuf + (((long long)b * Nn + n) << 10);
        const float wi = wrow[i];
        float eL[4];
        float s = 0.0f;
        #pragma unroll
        for (int k = 0; k < 4; k++) {
            int j = tid + k * 256;
            if (j < len) {
                float e = __expf(wi * wrow[j] * aL[k]);
                eL[k] = e; s += e;
            } else eL[k] = 0.0f;
        }
        s = blockSum(s, red);
        const float gsc = (1.0f / (1.0f + __expf(-gates[n]))) / (16.0f * s);
        #pragma unroll
        for (int k = 0; k < 4; k++) accL[k] += gsc * eL[k];
    }
    __nv_bfloat16* ph = Phi + ((long long)b << 20) + ((long long)i << 10);
    #pragma unroll
    for (int k = 0; k < 4; k++) {
        int j = tid + k * 256;
        ph[j] = __float2bfloat16(accL[k]);
    }
}

// ---------------- residual + LayerNorm ----------------
__global__ __launch_bounds__(256)
void final_ln_kernel(const float* __restrict__ x, const float* __restrict__ comb,
                     const float* __restrict__ rwp, const float* __restrict__ lnw,
                     const float* __restrict__ lnb, float* __restrict__ out)
{
    const int row = blockIdx.x;
    const int tid = threadIdx.x;
    __shared__ float red[9];
    const float rw = 1.0f / (1.0f + expf(-rwp[0]));
    const float om = 1.0f - rw;
    const float4 xv = ((const float4*)(x + (long long)row * Dd))[tid];
    const float4 cv = ((const float4*)(comb + (long long)row * Dd))[tid];
    float o0 = rw * xv.x + om * cv.x;
    float o1 = rw * xv.y + om * cv.y;
    float o2 = rw * xv.z + om * cv.z;
    float o3 = rw * xv.w + om * cv.w;
    float s = o0 + o1 + o2 + o3;
    float sq = o0 * o0 + o1 * o1 + o2 * o2 + o3 * o3;
    s = blockSum(s, red);
    __syncthreads();
    sq = blockSum(sq, red);
    const float mean = s * (1.0f / Dd);
    const float var = sq * (1.0f / Dd) - mean * mean;
    const float rstd = rsqrtf(var + 1e-5f);
    const float4 wv = ((const float4*)lnw)[tid];
    const float4 bv = ((const float4*)lnb)[tid];
    float4 ov;
    ov.x = (o0 - mean) * rstd * wv.x + bv.x;
    ov.y = (o1 - mean) * rstd * wv.y + bv.y;
    ov.z = (o2 - mean) * rstd * wv.z + bv.z;
    ov.w = (o3 - mean) * rstd * wv.w + bv.w;
    ((float4*)(out + (long long)row * Dd))[tid] = ov;
}

// ---------------- host launcher ----------------
static cudaStream_t g_s1, g_s2;
static cudaEvent_t g_evF1, g_evF2, g_evJ1, g_evJ2;

extern "C" void kernel_launch(void* const* d_in, const int* in_sizes, int n_in,
                              void* d_out, int out_size)
{
    const float* x        = (const float*)d_in[0];
    const float* posW     = (const float*)d_in[1];
    const float* posB     = (const float*)d_in[2];
    const float* posBias  = (const float*)d_in[3];
    const float* splatPos = (const float*)d_in[4];
    const float* logSc    = (const float*)d_in[5];
    const float* qW       = (const float*)d_in[6];
    const float* kW       = (const float*)d_in[7];
    const float* vW       = (const float*)d_in[8];
    const float* gates    = (const float*)d_in[9];
    const float* rwp      = (const float*)d_in[10];
    const float* lnw      = (const float*)d_in[11];
    const float* lnb      = (const float*)d_in[12];
    float* out = (float*)d_out;

    // one-time init (first call is the non-captured correctness run)
    static bool inited = []() {
        cudaFuncSetAttribute(hmma_gemm<0>, cudaFuncAttributeMaxDynamicSharedMemorySize, GSMEM);
        cudaFuncSetAttribute(hmma_gemm<1>, cudaFuncAttributeMaxDynamicSharedMemorySize, GSMEM);
        cudaFuncSetAttribute(hmma_gemm<2>, cudaFuncAttributeMaxDynamicSharedMemorySize, GSMEM);
        cudaStreamCreateWithFlags(&g_s1, cudaStreamNonBlocking);
        cudaStreamCreateWithFlags(&g_s2, cudaStreamNonBlocking);
        cudaEventCreateWithFlags(&g_evF1, cudaEventDisableTiming);
        cudaEventCreateWithFlags(&g_evF2, cudaEventDisableTiming);
        cudaEventCreateWithFlags(&g_evJ1, cudaEventDisableTiming);
        cudaEventCreateWithFlags(&g_evJ2, cudaEventDisableTiming);
        return true;
    }();
    (void)inited;

    float *A, *comb, *w;
    __nv_bfloat16 *xh, *wqh, *wkh, *wvh, *Qh, *Kh, *Vth, *Ph;
    cudaGetSymbolAddress((void**)&A, g_A);
    cudaGetSymbolAddress((void**)&comb, g_comb);
    cudaGetSymbolAddress((void**)&w, g_w);
    cudaGetSymbolAddress((void**)&xh, g_xh);
    cudaGetSymbolAddress((void**)&wqh, g_wqh);
    cudaGetSymbolAddress((void**)&wkh, g_wkh);
    cudaGetSymbolAddress((void**)&wvh, g_wvh);
    cudaGetSymbolAddress((void**)&Qh, g_Qh);
    cudaGetSymbolAddress((void**)&Kh, g_Kh);
    cudaGetSymbolAddress((void**)&Vth, g_Vth);
    cudaGetSymbolAddress((void**)&Ph, g_Ph);

    const float inv_sqrt_d = 1.0f / 32.0f;

    // fork: pos_influence on s1 (independent until pbar)
    cudaEventRecord(g_evF1, 0);
    cudaStreamWaitEvent(g_s1, g_evF1, 0);
    pos_influence_kernel<<<Mtot / 4, 256, 0, g_s1>>>(x, posW, posB, posBias, splatPos, logSc, w);
    cudaEventRecord(g_evJ1, g_s1);

    // fork: weight transpose on s2 (joins before QKV)
    cudaEventRecord(g_evF2, 0);
    cudaStreamWaitEvent(g_s2, g_evF2, 0);
    {
        TW3 tw = { qW, kW, vW, wqh, wkh, wvh };
        transpose_w3<<<dim3(32, 32, 3), 256, 0, g_s2>>>(tw);
    }
    cudaEventRecord(g_evJ2, g_s2);

    // main: x -> bf16
    splitH_kernel<<<(Mtot * Dd) / 256, 256>>>(x, xh, Mtot * Dd);
    cudaStreamWaitEvent(0, g_evJ2, 0);

    // QKV projections: z = 0(Q bf16) / 1(K bf16) / 2(V -> transposed bf16)
    {
        GemmArgs a = {};
        a.A = xh; a.sA = 0;
        a.B0 = wqh; a.B1 = wkh; a.B2 = wvh; a.sB = 0;
        a.Cb0 = Qh; a.Cb1 = Kh; a.Vt = Vth; a.sC = 0;
        a.M = Mtot; a.N = Dd; a.K = Dd; a.alpha = 1.0f;
        hmma_gemm<0><<<dim3(Dd / BN, Mtot / BM, 3), 256, GSMEM>>>(a);
    }
    // scores A = Q K^T / sqrt(d), lower-tri tiles only
    {
        GemmArgs a = {};
        a.A = Qh; a.sA = (long long)Ss * Dd;
        a.B0 = Kh; a.B1 = Kh; a.B2 = Kh; a.sB = (long long)Ss * Dd;
        a.Cf = A; a.sC = (long long)Ss * Ss;
        a.M = Ss; a.N = Ss; a.K = Dd; a.alpha = inv_sqrt_d;
        hmma_gemm<1><<<dim3(Ss / BN, Ss / BM, Bb), 256, GSMEM>>>(a);
    }
    // join influence, then aggregated softmax -> P̄
    cudaStreamWaitEvent(0, g_evJ1, 0);
    pbar_kernel<<<Mtot, 256>>>(A, w, gates, Ph);
    // comb = P̄ @ V (B = V^T [D,S]), causal K-truncation
    {
        GemmArgs a = {};
        a.A = Ph; a.sA = (long long)Ss * Ss;
        a.B0 = Vth; a.B1 = Vth; a.B2 = Vth; a.sB = (long long)Dd * Ss;
        a.Cf = comb; a.sC = (long long)Ss * Dd;
        a.M = Ss; a.N = Dd; a.K = Ss; a.alpha = 1.0f;
        hmma_gemm<2><<<dim3(Dd / BN, Ss / BM, Bb), 256, GSMEM>>>(a);
    }
    // residual + LayerNorm
    final_ln_kernel<<<Mtot, 256>>>(x, comb, rwp, lnw, lnb, out);
}

// round 9
// speedup vs baseline: 6.1636x; 1.0246x over previous
#include <cuda_runtime.h>
#include <cuda_bf16.h>
#include <math.h>
#include <stdint.h>

#define Bb 2
#define Ss 1024
#define Dd 1024
#define Ee 64
#define Nn 16
#define Mtot (Bb * Ss)

// ---------------- scratch (no allocation allowed) ----------------
__device__ float g_A[Bb * Ss * Ss];        // QK^T/sqrt(d) fp32
__device__ float g_comb[Bb * Ss * Dd];
__device__ float g_w[Bb * Nn * Ss];
__device__ __nv_bfloat16 g_xh[Mtot * Dd];
__device__ __nv_bfloat16 g_wqh[Dd * Dd];
__device__ __nv_bfloat16 g_wkh[Dd * Dd];
__device__ __nv_bfloat16 g_wvh[Dd * Dd];
__device__ __nv_bfloat16 g_Qh[Mtot * Dd];
__device__ __nv_bfloat16 g_Kh[Mtot * Dd];
__device__ __nv_bfloat16 g_Vth[Bb * Dd * Ss];   // V^T bf16, [b][d][s]
__device__ __nv_bfloat16 g_Ph[Bb * Ss * Ss];

// ---------------- helpers ----------------
__device__ __forceinline__ uint32_t smem_u32(const void* p) {
    uint32_t a;
    asm("{ .reg .u64 t; cvta.to.shared.u64 t, %1; cvt.u32.u64 %0, t; }" : "=r"(a) : "l"(p));
    return a;
}
// SW128 swizzle for 128B rows
__device__ __forceinline__ uint32_t sw128(uint32_t off) { return off ^ ((off >> 3) & 0x70); }

#define CP_ASYNC16(s, g) \
    asm volatile("cp.async.cg.shared.global [%0], [%1], 16;" :: "r"(s), "l"(g) : "memory")
#define CP_COMMIT() asm volatile("cp.async.commit_group;" ::: "memory")
#define CP_WAIT1()  asm volatile("cp.async.wait_group 1;" ::: "memory")

#define LDSM_X4(r0, r1, r2, r3, addr) \
    asm volatile("ldmatrix.sync.aligned.m8n8.x4.shared.b16 {%0,%1,%2,%3}, [%4];" \
        : "=r"(r0), "=r"(r1), "=r"(r2), "=r"(r3) : "r"(addr) : "memory")

#define MMA16816(ac, a, b0, b1) \
    asm volatile("mma.sync.aligned.m16n8k16.row.col.f32.bf16.bf16.f32 " \
        "{%0,%1,%2,%3}, {%4,%5,%6,%7}, {%8,%9}, {%0,%1,%2,%3};" \
        : "+f"((ac)[0]), "+f"((ac)[1]), "+f"((ac)[2]), "+f"((ac)[3]) \
        : "r"((a)[0]), "r"((a)[1]), "r"((a)[2]), "r"((a)[3]), "r"(b0), "r"(b1))

// ---------------- reductions ----------------
__device__ __forceinline__ float warpSum(float v) {
    #pragma unroll
    for (int o = 16; o; o >>= 1) v += __shfl_xor_sync(0xffffffffu, v, o);
    return v;
}
__device__ __forceinline__ float blockSum(float v, float* red) {
    int lane = threadIdx.x & 31, w = threadIdx.x >> 5;
    v = warpSum(v);
    if (lane == 0) red[w] = v;
    __syncthreads();
    if (w == 0) {
        float t = (lane < 8) ? red[lane] : 0.0f;
        t = warpSum(t);
        if (lane == 0) red[8] = t;
    }
    __syncthreads();
    return red[8];
}

// ---------------- single-pass bf16 HMMA GEMM (generalized tiles) ----------------
// D[M,N] = alpha * A[M,K] @ B[N,K]^T, 256 threads, warp grid WMxWN, warptile (BMp/WM)x(BNp/WN)
#define BKC 64
#define NSTAGE 3

struct GemmArgs {
    const __nv_bfloat16* A; long long sA;
    const __nv_bfloat16 *B0, *B1, *B2; long long sB;
    float* Cf;                       // fp32 out (score/PV)
    __nv_bfloat16 *Cb0, *Cb1;        // bf16 out (Q,K)
    __nv_bfloat16* Vt;               // transposed bf16 out (V-only launch)
    long long sC;
    int M, N, K; float alpha;
};

// CAUSAL: 0=proj (Vt? transposed epilogue), 1=score (skip upper tiles), 2=PV (K-truncate)
template <int CAUSAL, int BMp, int BNp, int WM, int WN>
__global__ __launch_bounds__(256)
void hmma_gemm(GemmArgs g)
{
    constexpr int STG_A = BMp * 128;        // bytes per A stage
    constexpr int STG_B = BNp * 128;
    constexpr int WTM = BMp / WM;           // warptile M
    constexpr int WTN = BNp / WN;
    constexpr int MF = WTM / 16;
    constexpr int NG = WTN / 16;

    const int bx = blockIdx.x, by = blockIdx.y, bz = blockIdx.z;
    if (CAUSAL == 1 && bx * BNp >= (by + 1) * BMp) return;
    int kEnd = g.K;
    if (CAUSAL == 2) kEnd = min(g.K, (by + 1) * BMp);
    const int NC = kEnd / BKC;

    extern __shared__ __align__(128) char dsm[];
    const uint32_t sAb = smem_u32(dsm);
    const uint32_t sBb = sAb + NSTAGE * STG_A;

    const int tid = threadIdx.x, wid = tid >> 5, lane = tid & 31;
    const int warpM = wid / WN, warpN = wid % WN;

    const __nv_bfloat16* Ah = g.A + bz * g.sA;
    const __nv_bfloat16* Bh = (bz == 0 ? g.B0 : bz == 1 ? g.B1 : g.B2) + bz * g.sB;

    float acc[MF][NG * 2][4];
    #pragma unroll
    for (int i = 0; i < MF; i++)
        #pragma unroll
        for (int j = 0; j < NG * 2; j++)
            #pragma unroll
            for (int k = 0; k < 4; k++) acc[i][j][k] = 0.0f;

    const int lc16 = tid & 7;
    const int lrow = tid >> 3;       // 0..31

    const __nv_bfloat16* Arow = Ah + (long long)(by * BMp) * g.K;
    const __nv_bfloat16* Brow = Bh + (long long)(bx * BNp) * g.K;
    const int Kld = g.K;

    auto issue = [&](int it, int buf) {
        const int k0 = it * BKC;
        const uint32_t aB = sAb + buf * STG_A;
        const uint32_t bB = sBb + buf * STG_B;
        #pragma unroll
        for (int r = 0; r < BMp / 32; r++) {
            const int row = lrow + 32 * r;
            CP_ASYNC16(aB + sw128(row * 128 + lc16 * 16),
                       Arow + (long long)row * Kld + k0 + lc16 * 8);
        }
        #pragma unroll
        for (int r = 0; r < BNp / 32; r++) {
            const int row = lrow + 32 * r;
            CP_ASYNC16(bB + sw128(row * 128 + lc16 * 16),
                       Brow + (long long)row * Kld + k0 + lc16 * 8);
        }
    };

    issue(0, 0); CP_COMMIT();
    if (NC > 1) issue(1, 1);
    CP_COMMIT();

    const int aRowL = (lane & 15);
    const int aHiK  = (lane >> 4);
    const int bRowL = ((lane & 16) >> 1) + (lane & 7);
    const int bHiK  = ((lane >> 3) & 1);

    #pragma unroll 1
    for (int it = 0; it < NC; it++) {
        CP_WAIT1();
        __syncthreads();
        const int nx = it + 2;
        if (nx < NC) issue(nx, nx % 3);
        CP_COMMIT();
        const int buf = it % 3;
        const uint32_t aB = sAb + buf * STG_A;
        const uint32_t bB = sBb + buf * STG_B;
        #pragma unroll
        for (int s = 0; s < 4; s++) {
            uint32_t ra[MF][4], rb[NG][4];
            #pragma unroll
            for (int mf = 0; mf < MF; mf++) {
                int row = warpM * WTM + mf * 16 + aRowL;
                int c16 = s * 2 + aHiK;
                LDSM_X4(ra[mf][0], ra[mf][1], ra[mf][2], ra[mf][3],
                        aB + sw128(row * 128 + c16 * 16));
            }
            #pragma unroll
            for (int ng = 0; ng < NG; ng++) {
                int nrow = warpN * WTN + ng * 16 + bRowL;
                int c16 = s * 2 + bHiK;
                LDSM_X4(rb[ng][0], rb[ng][1], rb[ng][2], rb[ng][3],
                        bB + sw128(nrow * 128 + c16 * 16));
            }
            #pragma unroll
            for (int mf = 0; mf < MF; mf++)
                #pragma unroll
                for (int ng = 0; ng < NG; ng++) {
                    MMA16816(acc[mf][ng * 2 + 0], ra[mf], rb[ng][0], rb[ng][1]);
                    MMA16816(acc[mf][ng * 2 + 1], ra[mf], rb[ng][2], rb[ng][3]);
                }
        }
    }

    const float al = g.alpha;

    if (CAUSAL == 0 && g.Vt) {
        // ---------- V epilogue: transpose via smem, write bf16 V^T (128x128 tiles) ----------
        __nv_bfloat16 (*st)[136] = (__nv_bfloat16 (*)[136])dsm;
        __syncthreads();
        #pragma unroll
        for (int mf = 0; mf < MF; mf++) {
            const int r_l = warpM * WTM + mf * 16 + (lane >> 2);
            #pragma unroll
            for (int nf = 0; nf < NG * 2; nf++) {
                const int c_l = warpN * WTN + nf * 8 + (lane & 3) * 2;
                st[c_l][r_l]         = __float2bfloat16(acc[mf][nf][0]);
                st[c_l + 1][r_l]     = __float2bfloat16(acc[mf][nf][1]);
                st[c_l][r_l + 8]     = __float2bfloat16(acc[mf][nf][2]);
                st[c_l + 1][r_l + 8] = __float2bfloat16(acc[mf][nf][3]);
            }
        }
        __syncthreads();
        const int rb_ = by >> 3;
        const int s0 = (by & 7) * 128;
        const int d = tid >> 1;
        const int so = (tid & 1) * 64;
        const uint4* src = (const uint4*)&st[d][so];
        uint4* dst = (uint4*)(g.Vt + (long long)rb_ * Dd * Ss
                              + (long long)(bx * BNp + d) * Ss + s0 + so);
        #pragma unroll
        for (int i = 0; i < 8; i++) dst[i] = src[i];
        return;
    }

    // ---------------- standard epilogue ----------------
    __nv_bfloat16* Cb = (CAUSAL == 0) ? (bz == 0 ? g.Cb0 : g.Cb1) : nullptr;
    float* Cf = g.Cf;
    #pragma unroll
    for (int mf = 0; mf < MF; mf++) {
        const long long r0 = (long long)(by * BMp + warpM * WTM + mf * 16 + (lane >> 2));
        const long long r1 = r0 + 8;
        #pragma unroll
        for (int nf = 0; nf < NG * 2; nf++) {
            const int c0 = bx * BNp + warpN * WTN + nf * 8 + (lane & 3) * 2;
            float v00 = acc[mf][nf][0] * al, v01 = acc[mf][nf][1] * al;
            float v10 = acc[mf][nf][2] * al, v11 = acc[mf][nf][3] * al;
            if (CAUSAL == 0) {
                __nv_bfloat162 p0, p1;
                p0.x = __float2bfloat16(v00); p0.y = __float2bfloat16(v01);
                p1.x = __float2bfloat16(v10); p1.y = __float2bfloat16(v11);
                *(__nv_bfloat162*)(Cb + bz * g.sC + r0 * g.N + c0) = p0;
                *(__nv_bfloat162*)(Cb + bz * g.sC + r1 * g.N + c0) = p1;
            } else {
                *(float2*)(Cf + bz * g.sC + r0 * g.N + c0) = make_float2(v00, v01);
                *(float2*)(Cf + bz * g.sC + r1 * g.N + c0) = make_float2(v10, v11);
            }
        }
    }
}

// instantiation aliases
constexpr int SM_QKV = (128 + 128) * 128 * NSTAGE;   // 98304
constexpr int SM_SC  = (128 + 64) * 128 * NSTAGE;    // 73728
constexpr int SM_PV  = (64 + 128) * 128 * NSTAGE;    // 73728

// ---------------- elementwise bf16 cast ----------------
__global__ __launch_bounds__(256)
void splitH_kernel(const float* __restrict__ in, __nv_bfloat16* __restrict__ h, int n)
{
    int i = blockIdx.x * 256 + threadIdx.x;
    if (i < n) h[i] = __float2bfloat16(in[i]);
}

// merged 3-weight transpose (z selects q/k/v), bf16 out
struct TW3 { const float *i0, *i1, *i2; __nv_bfloat16 *h0, *h1, *h2; };
__global__ __launch_bounds__(256)
void transpose_w3(TW3 a)
{
    const int z = blockIdx.z;
    const float* in = (z == 0 ? a.i0 : z == 1 ? a.i1 : a.i2);
    __nv_bfloat16* oh = (z == 0 ? a.h0 : z == 1 ? a.h1 : a.h2);
    __shared__ float t[32][33];
    const int c0 = blockIdx.x * 32, r0 = blockIdx.y * 32;
    const int x = threadIdx.x & 31, y = threadIdx.x >> 5;
    #pragma unroll
    for (int r = y; r < 32; r += 8) t[r][x] = in[(long long)(r0 + r) * Dd + c0 + x];
    __syncthreads();
    #pragma unroll
    for (int r = y; r < 32; r += 8)
        oh[(long long)(c0 + r) * Dd + r0 + x] = __float2bfloat16(t[x][r]);
}

// ---------------- positions + splat influence: 4 tokens / 256 threads ----------------
__global__ __launch_bounds__(256)
void pos_influence_kernel(const float* __restrict__ x, const float* __restrict__ posW,
                          const float* __restrict__ posB, const float* __restrict__ posBias,
                          const float* __restrict__ splatPos, const float* __restrict__ logScales,
                          float* __restrict__ wout)
{
    const int t0 = blockIdx.x * 4;
    const int b = t0 >> 10;
    const int s0 = t0 & 1023;
    __shared__ float xs[4][Dd];
    __shared__ float pos[4][Ee];
    const int tid = threadIdx.x;
    const int e = tid & 63, tg = tid >> 6;
    for (int i = tid; i < 4 * Dd; i += 256)
        xs[i >> 10][i & 1023] = x[(long long)t0 * Dd + i];
    __syncthreads();
    float acc = posB[e];
    const float* xr = xs[tg];
    #pragma unroll 8
    for (int d = 0; d < Dd; d++) acc += xr[d] * __ldg(&posW[d * Ee + e]);
    pos[tg][e] = tanhf(acc) + posBias[(s0 + tg) * Ee + e];
    __syncthreads();
    if (tid < 64) {
        const int n = tid & 15, tk = tid >> 4;
        float sc = expf(logScales[n]);
        sc = fminf(fmaxf(sc, 0.3f), 2.0f);
        float dsq = 0.0f;
        #pragma unroll
        for (int j = 0; j < Ee; j++) {
            float d = pos[tk][j] - splatPos[n * Ee + j];
            dsq += d * d;
        }
        float inf = fmaxf(__expf(-0.5f * dsq / (sc * sc)), 0.01f);
        wout[((long long)b * Nn + n) * Ss + s0 + tk] = inf;
    }
}

// ---------------- aggregated softmax -> P̄ (bf16) ----------------
__global__ __launch_bounds__(256)
void pbar_kernel(const float* __restrict__ Abuf, const float* __restrict__ wbuf,
                 const float* __restrict__ gates, __nv_bfloat16* __restrict__ Phi)
{
    const int row = blockIdx.x;
    const int b = row >> 10, i = row & 1023;
    const float* Arow = Abuf + ((long long)b << 20) + ((long long)i << 10);
    const int tid = threadIdx.x;
    const int len = i + 1;
    __shared__ float red[9];
    float aL[4], accL[4] = {0, 0, 0, 0};
    #pragma unroll
    for (int k = 0; k < 4; k++) {
        int j = tid + k * 256;
        aL[k] = (j < len) ? Arow[j] : 0.0f;
    }
    #pragma unroll 1
    for (int n = 0; n < Nn; n++) {
        const float* wrow = wbuf + (((long long)b * Nn + n) << 10);
        const float wi = wrow[i];
        float eL[4];
        float s = 0.0f;
        #pragma unroll
        for (int k = 0; k < 4; k++) {
            int j = tid + k * 256;
            if (j < len) {
                float e = __expf(wi * wrow[j] * aL[k]);
                eL[k] = e; s += e;
            } else eL[k] = 0.0f;
        }
        s = blockSum(s, red);
        const float gsc = (1.0f / (1.0f + __expf(-gates[n]))) / (16.0f * s);
        #pragma unroll
        for (int k = 0; k < 4; k++) accL[k] += gsc * eL[k];
    }
    __nv_bfloat16* ph = Phi + ((long long)b << 20) + ((long long)i << 10);
    #pragma unroll
    for (int k = 0; k < 4; k++) {
        int j = tid + k * 256;
        ph[j] = __float2bfloat16(accL[k]);
    }
}

// ---------------- residual + LayerNorm ----------------
__global__ __launch_bounds__(256)
void final_ln_kernel(const float* __restrict__ x, const float* __restrict__ comb,
                     const float* __restrict__ rwp, const float* __restrict__ lnw,
                     const float* __restrict__ lnb, float* __restrict__ out)
{
    const int row = blockIdx.x;
    const int tid = threadIdx.x;
    __shared__ float red[9];
    const float rw = 1.0f / (1.0f + expf(-rwp[0]));
    const float om = 1.0f - rw;
    const float4 xv = ((const float4*)(x + (long long)row * Dd))[tid];
    const float4 cv = ((const float4*)(comb + (long long)row * Dd))[tid];
    float o0 = rw * xv.x + om * cv.x;
    float o1 = rw * xv.y + om * cv.y;
    float o2 = rw * xv.z + om * cv.z;
    float o3 = rw * xv.w + om * cv.w;
    float s = o0 + o1 + o2 + o3;
    float sq = o0 * o0 + o1 * o1 + o2 * o2 + o3 * o3;
    s = blockSum(s, red);
    __syncthreads();
    sq = blockSum(sq, red);
    const float mean = s * (1.0f / Dd);
    const float var = sq * (1.0f / Dd) - mean * mean;
    const float rstd = rsqrtf(var + 1e-5f);
    const float4 wv = ((const float4*)lnw)[tid];
    const float4 bv = ((const float4*)lnb)[tid];
    float4 ov;
    ov.x = (o0 - mean) * rstd * wv.x + bv.x;
    ov.y = (o1 - mean) * rstd * wv.y + bv.y;
    ov.z = (o2 - mean) * rstd * wv.z + bv.z;
    ov.w = (o3 - mean) * rstd * wv.w + bv.w;
    ((float4*)(out + (long long)row * Dd))[tid] = ov;
}

// ---------------- host launcher ----------------
static cudaStream_t g_s1, g_s2;
static cudaEvent_t g_evF1, g_evF2, g_evX, g_evJ1, g_evJ2, g_evV;

extern "C" void kernel_launch(void* const* d_in, const int* in_sizes, int n_in,
                              void* d_out, int out_size)
{
    const float* x        = (const float*)d_in[0];
    const float* posW     = (const float*)d_in[1];
    const float* posB     = (const float*)d_in[2];
    const float* posBias  = (const float*)d_in[3];
    const float* splatPos = (const float*)d_in[4];
    const float* logSc    = (const float*)d_in[5];
    const float* qW       = (const float*)d_in[6];
    const float* kW       = (const float*)d_in[7];
    const float* vW       = (const float*)d_in[8];
    const float* gates    = (const float*)d_in[9];
    const float* rwp      = (const float*)d_in[10];
    const float* lnw      = (const float*)d_in[11];
    const float* lnb      = (const float*)d_in[12];
    float* out = (float*)d_out;

    static bool inited = []() {
        cudaFuncSetAttribute((const void*)hmma_gemm<0, 128, 128, 4, 2>,
                             cudaFuncAttributeMaxDynamicSharedMemorySize, SM_QKV);
        cudaFuncSetAttribute((const void*)hmma_gemm<1, 128, 64, 4, 2>,
                             cudaFuncAttributeMaxDynamicSharedMemorySize, SM_SC);
        cudaFuncSetAttribute((const void*)hmma_gemm<2, 64, 128, 2, 4>,
                             cudaFuncAttributeMaxDynamicSharedMemorySize, SM_PV);
        cudaStreamCreateWithFlags(&g_s1, cudaStreamNonBlocking);
        cudaStreamCreateWithFlags(&g_s2, cudaStreamNonBlocking);
        cudaEventCreateWithFlags(&g_evF1, cudaEventDisableTiming);
        cudaEventCreateWithFlags(&g_evF2, cudaEventDisableTiming);
        cudaEventCreateWithFlags(&g_evX, cudaEventDisableTiming);
        cudaEventCreateWithFlags(&g_evJ1, cudaEventDisableTiming);
        cudaEventCreateWithFlags(&g_evJ2, cudaEventDisableTiming);
        cudaEventCreateWithFlags(&g_evV, cudaEventDisableTiming);
        return true;
    }();
    (void)inited;

    float *A, *comb, *w;
    __nv_bfloat16 *xh, *wqh, *wkh, *wvh, *Qh, *Kh, *Vth, *Ph;
    cudaGetSymbolAddress((void**)&A, g_A);
    cudaGetSymbolAddress((void**)&comb, g_comb);
    cudaGetSymbolAddress((void**)&w, g_w);
    cudaGetSymbolAddress((void**)&xh, g_xh);
    cudaGetSymbolAddress((void**)&wqh, g_wqh);
    cudaGetSymbolAddress((void**)&wkh, g_wkh);
    cudaGetSymbolAddress((void**)&wvh, g_wvh);
    cudaGetSymbolAddress((void**)&Qh, g_Qh);
    cudaGetSymbolAddress((void**)&Kh, g_Kh);
    cudaGetSymbolAddress((void**)&Vth, g_Vth);
    cudaGetSymbolAddress((void**)&Ph, g_Ph);

    const float inv_sqrt_d = 1.0f / 32.0f;

    // fork: pos_influence on s1 (joins before pbar)
    cudaEventRecord(g_evF1, 0);
    cudaStreamWaitEvent(g_s1, g_evF1, 0);
    pos_influence_kernel<<<Mtot / 4, 256, 0, g_s1>>>(x, posW, posB, posBias, splatPos, logSc, w);
    cudaEventRecord(g_evJ1, g_s1);

    // fork: weight transpose on s2
    cudaEventRecord(g_evF2, 0);
    cudaStreamWaitEvent(g_s2, g_evF2, 0);
    {
        TW3 tw = { qW, kW, vW, wqh, wkh, wvh };
        transpose_w3<<<dim3(32, 32, 3), 256, 0, g_s2>>>(tw);
    }
    cudaEventRecord(g_evJ2, g_s2);

    // main: x -> bf16
    splitH_kernel<<<(Mtot * Dd) / 256, 256>>>(x, xh, Mtot * Dd);
    cudaEventRecord(g_evX, 0);

    // V projection on s2 (needs xh + wvh); off critical path until PV
    cudaStreamWaitEvent(g_s2, g_evX, 0);
    {
        GemmArgs a = {};
        a.A = xh; a.sA = 0;
        a.B0 = wvh; a.B1 = wvh; a.B2 = wvh; a.sB = 0;
        a.Vt = Vth; a.sC = 0;
        a.M = Mtot; a.N = Dd; a.K = Dd; a.alpha = 1.0f;
        hmma_gemm<0, 128, 128, 4, 2><<<dim3(Dd / 128, Mtot / 128, 1), 256, SM_QKV, g_s2>>>(a);
    }
    cudaEventRecord(g_evV, g_s2);

    // main: Q,K projections (need wqh/wkh from s2's transpose)
    cudaStreamWaitEvent(0, g_evJ2, 0);
    {
        GemmArgs a = {};
        a.A = xh; a.sA = 0;
        a.B0 = wqh; a.B1 = wkh; a.B2 = wkh; a.sB = 0;
        a.Cb0 = Qh; a.Cb1 = Kh; a.sC = 0;
        a.M = Mtot; a.N = Dd; a.K = Dd; a.alpha = 1.0f;
        hmma_gemm<0, 128, 128, 4, 2><<<dim3(Dd / 128, Mtot / 128, 2), 256, SM_QKV>>>(a);
    }
    // scores A = Q K^T / sqrt(d), 128x64 tiles, lower-tri only
    {
        GemmArgs a = {};
        a.A = Qh; a.sA = (long long)Ss * Dd;
        a.B0 = Kh; a.B1 = Kh; a.B2 = Kh; a.sB = (long long)Ss * Dd;
        a.Cf = A; a.sC = (long long)Ss * Ss;
        a.M = Ss; a.N = Ss; a.K = Dd; a.alpha = inv_sqrt_d;
        hmma_gemm<1, 128, 64, 4, 2><<<dim3(Ss / 64, Ss / 128, Bb), 256, SM_SC>>>(a);
    }
    // join influence -> pbar
    cudaStreamWaitEvent(0, g_evJ1, 0);
    pbar_kernel<<<Mtot, 256>>>(A, w, gates, Ph);
    // join V -> PV: comb = P̄ @ V, 64x128 tiles, K-truncated
    cudaStreamWaitEvent(0, g_evV, 0);
    {
        GemmArgs a = {};
        a.A = Ph; a.sA = (long long)Ss * Ss;
        a.B0 = Vth; a.B1 = Vth; a.B2 = Vth; a.sB = (long long)Dd * Ss;
        a.Cf = comb; a.sC = (long long)Ss * Dd;
        a.M = Ss; a.N = Dd; a.K = Ss; a.alpha = 1.0f;
        hmma_gemm<2, 64, 128, 2, 4><<<dim3(Dd / 128, Ss / 64, Bb), 256, SM_PV>>>(a);
    }
    // residual + LayerNorm
    final_ln_kernel<<<Mtot, 256>>>(x, comb, rwp, lnw, lnb, out);
}